// round 1
// baseline (speedup 1.0000x reference)
#include <cuda_runtime.h>

// Problem constants
#define T_DIM 1024
#define B_DIM 4
#define E_DIM 512
#define H_DIM 8
#define HD    64
#define BH    32          // B*H
#define M_ROWS 4096       // T*B

// ---------------------------------------------------------------------------
// Scratch (device globals; no allocations allowed in kernel_launch)
// ---------------------------------------------------------------------------
__device__ float g_q[BH * T_DIM * HD];        // 8 MB  (scaled by 1/8)
__device__ float g_k[BH * T_DIM * HD];        // 8 MB
__device__ float g_v[BH * T_DIM * HD];        // 8 MB
__device__ float g_attnout[M_ROWS * E_DIM];   // 8 MB  ([T,B,E] layout)
__device__ float g_bias[BH * T_DIM * T_DIM];  // 134 MB (transposed dist)

// ---------------------------------------------------------------------------
// Helpers
// ---------------------------------------------------------------------------
__device__ __forceinline__ unsigned f2tf32(float x) {
    unsigned y;
    asm("cvt.rna.tf32.f32 %0, %1;" : "=r"(y) : "f"(x));
    return y;
}

__device__ __forceinline__ void mma_tf32(float c[4], const unsigned a[4],
                                         unsigned b0, unsigned b1) {
    asm volatile(
        "mma.sync.aligned.m16n8k8.row.col.f32.tf32.tf32.f32 "
        "{%0,%1,%2,%3}, {%4,%5,%6,%7}, {%8,%9}, {%0,%1,%2,%3};\n"
        : "+f"(c[0]), "+f"(c[1]), "+f"(c[2]), "+f"(c[3])
        : "r"(a[0]), "r"(a[1]), "r"(a[2]), "r"(a[3]), "r"(b0), "r"(b1));
}

// ---------------------------------------------------------------------------
// Kernel 1: dist [B,T,T,H] -> g_bias [B*H, T, T]   (fully coalesced both sides)
// ---------------------------------------------------------------------------
__global__ void bias_transpose_kernel(const float* __restrict__ dist) {
    __shared__ float sm[H_DIM][264];   // [h][256 s], pad to dodge conflicts
    const int sc  = blockIdx.x;        // s chunk: 0..3 (256 each)
    const int t   = blockIdx.y;        // 0..1023
    const int b   = blockIdx.z;        // 0..3
    const int tid = threadIdx.x;       // 256 threads

    const float* src = dist + (((size_t)(b * T_DIM + t)) * T_DIM + sc * 256) * H_DIM;
    // thread tid loads the 8 contiguous h-values of s = sc*256 + tid
    float4 v0 = *(const float4*)(src + (size_t)tid * 8);
    float4 v1 = *(const float4*)(src + (size_t)tid * 8 + 4);
    sm[0][tid] = v0.x; sm[1][tid] = v0.y; sm[2][tid] = v0.z; sm[3][tid] = v0.w;
    sm[4][tid] = v1.x; sm[5][tid] = v1.y; sm[6][tid] = v1.z; sm[7][tid] = v1.w;
    __syncthreads();

#pragma unroll
    for (int h = 0; h < H_DIM; h++) {
        size_t dst = (((size_t)(b * H_DIM + h) * T_DIM + t) * T_DIM) + sc * 256 + tid;
        g_bias[dst] = sm[h][tid];
    }
}

// ---------------------------------------------------------------------------
// Kernel 2/4: tf32 GEMM  C[M,N] = A[M,K] @ W[N,K]^T + bias
//   mode 0: A=query (M=4096,K=512,N=1536), epilogue scatters into g_q/g_k/g_v
//   mode 1: A=g_attnout (M=4096,K=512,N=512), epilogue writes d_out + bias
// Block tile 64x64, BK=16, 128 threads (4 warps in 2x2, each warp 32x32).
// ---------------------------------------------------------------------------
__device__ __forceinline__ void qkv_store(int m, int n, float val,
                                          const float* __restrict__ bias) {
    val += bias[n];
    const int sec = n >> 9;      // 0:q 1:k 2:v
    const int e   = n & 511;
    const int h   = e >> 6;
    const int d   = e & 63;
    const int tt  = m >> 2;      // token (m = t*4 + b)
    const int bb  = m & 3;
    const int idx = (((bb << 3) + h) << 16) + (tt << 6) + d;  // ((b*8+h)*1024+t)*64+d
    if (sec == 0)      g_q[idx] = val * 0.125f;   // 1/sqrt(64)
    else if (sec == 1) g_k[idx] = val;
    else               g_v[idx] = val;
}

__global__ void gemm_tf32_kernel(const float* __restrict__ A_in,
                                 const float* __restrict__ W,
                                 const float* __restrict__ bias,
                                 float* __restrict__ Cout,
                                 int K, int mode) {
    __shared__ unsigned As[64 * 20];  // stride 20 (==20 mod 32): conflict-free frags
    __shared__ unsigned Bs[64 * 20];

    const float* __restrict__ A = (mode == 0) ? A_in : g_attnout;

    const int tid  = threadIdx.x;
    const int lane = tid & 31;
    const int w    = tid >> 5;
    const int g    = lane >> 2;
    const int t4   = lane & 3;
    const int wm   = (w >> 1) * 32;
    const int wn   = (w & 1) * 32;
    const int bm0  = blockIdx.y * 64;
    const int bn0  = blockIdx.x * 64;

    float acc[2][4][4];
#pragma unroll
    for (int mi = 0; mi < 2; mi++)
#pragma unroll
        for (int ni = 0; ni < 4; ni++)
#pragma unroll
            for (int i = 0; i < 4; i++) acc[mi][ni][i] = 0.f;

    const int nkt = K >> 4;
    for (int kt = 0; kt < nkt; kt++) {
#pragma unroll
        for (int i = 0; i < 2; i++) {
            int v = tid + i * 128;            // 0..255 over 64 rows x 4 vec4
            int r = v >> 2;
            int c = (v & 3) * 4;
            float4 xa = *(const float4*)(A + (size_t)(bm0 + r) * K + kt * 16 + c);
            As[r * 20 + c + 0] = f2tf32(xa.x);
            As[r * 20 + c + 1] = f2tf32(xa.y);
            As[r * 20 + c + 2] = f2tf32(xa.z);
            As[r * 20 + c + 3] = f2tf32(xa.w);
            float4 xb = *(const float4*)(W + (size_t)(bn0 + r) * K + kt * 16 + c);
            Bs[r * 20 + c + 0] = f2tf32(xb.x);
            Bs[r * 20 + c + 1] = f2tf32(xb.y);
            Bs[r * 20 + c + 2] = f2tf32(xb.z);
            Bs[r * 20 + c + 3] = f2tf32(xb.w);
        }
        __syncthreads();

#pragma unroll
        for (int ks = 0; ks < 2; ks++) {
            const int k0 = ks * 8;
            unsigned a[2][4], bf[4][2];
#pragma unroll
            for (int mi = 0; mi < 2; mi++) {
                int r = wm + mi * 16 + g;
                a[mi][0] = As[r * 20 + k0 + t4];
                a[mi][1] = As[(r + 8) * 20 + k0 + t4];
                a[mi][2] = As[r * 20 + k0 + t4 + 4];
                a[mi][3] = As[(r + 8) * 20 + k0 + t4 + 4];
            }
#pragma unroll
            for (int ni = 0; ni < 4; ni++) {
                int n = wn + ni * 8 + g;
                bf[ni][0] = Bs[n * 20 + k0 + t4];
                bf[ni][1] = Bs[n * 20 + k0 + t4 + 4];
            }
#pragma unroll
            for (int mi = 0; mi < 2; mi++)
#pragma unroll
                for (int ni = 0; ni < 4; ni++)
                    mma_tf32(acc[mi][ni], a[mi], bf[ni][0], bf[ni][1]);
        }
        __syncthreads();
    }

    // epilogue
#pragma unroll
    for (int mi = 0; mi < 2; mi++) {
#pragma unroll
        for (int ni = 0; ni < 4; ni++) {
            int m = bm0 + wm + mi * 16 + g;
            int n = bn0 + wn + ni * 8 + t4 * 2;
            if (mode == 0) {
                qkv_store(m,     n,     acc[mi][ni][0], bias);
                qkv_store(m,     n + 1, acc[mi][ni][1], bias);
                qkv_store(m + 8, n,     acc[mi][ni][2], bias);
                qkv_store(m + 8, n + 1, acc[mi][ni][3], bias);
            } else {
                Cout[(size_t)m * 512 + n]           = acc[mi][ni][0] + bias[n];
                Cout[(size_t)m * 512 + n + 1]       = acc[mi][ni][1] + bias[n + 1];
                Cout[(size_t)(m + 8) * 512 + n]     = acc[mi][ni][2] + bias[n];
                Cout[(size_t)(m + 8) * 512 + n + 1] = acc[mi][ni][3] + bias[n + 1];
            }
        }
    }
}

// ---------------------------------------------------------------------------
// Kernel 3: fused flash attention, tf32 mma
//   grid (16 q-tiles, 32 heads); 128 threads = 4 warps, warp w owns rows
//   w*16..w*16+15 of the 64-row q tile. Online softmax over 16 s-tiles of 64.
// ---------------------------------------------------------------------------
#define ATT_STRIDE 68        // 68 mod 32 == 4 -> conflict-free fragment access
#define ATT_SMEM_WORDS (4 * 64 * ATT_STRIDE)
#define ATT_SMEM_BYTES (ATT_SMEM_WORDS * 4)

__global__ void attn_kernel() {
    extern __shared__ unsigned smem[];
    unsigned* Qs  = smem;                     // [64][68] tf32, rows=q, cols=d
    unsigned* Ks  = smem + 64 * ATT_STRIDE;   // rows=s, cols=d
    unsigned* Vts = smem + 2 * 64 * ATT_STRIDE; // rows=d, cols=s  (V transposed)
    unsigned* Ps  = smem + 3 * 64 * ATT_STRIDE; // rows=q, cols=s

    const int qt   = blockIdx.x;   // 0..15
    const int bh   = blockIdx.y;   // 0..31
    const int tid  = threadIdx.x;
    const int lane = tid & 31;
    const int w    = tid >> 5;
    const int g    = lane >> 2;
    const int t4   = lane & 3;
    const int row_s = w * 16;

    const float* __restrict__ Qg = g_q + ((size_t)bh * T_DIM + qt * 64) * HD;
    const float* __restrict__ Kg = g_k + (size_t)bh * T_DIM * HD;
    const float* __restrict__ Vg = g_v + (size_t)bh * T_DIM * HD;
    const float* __restrict__ Bg = g_bias + (size_t)bh * T_DIM * T_DIM;

    // load Q tile (64x64) -> Qs
#pragma unroll
    for (int i = 0; i < 8; i++) {
        int v = tid + i * 128;           // 1024 vec4
        int r = v >> 4;
        int c = (v & 15) * 4;
        float4 x = *(const float4*)(Qg + (size_t)r * HD + c);
        Qs[r * ATT_STRIDE + c + 0] = f2tf32(x.x);
        Qs[r * ATT_STRIDE + c + 1] = f2tf32(x.y);
        Qs[r * ATT_STRIDE + c + 2] = f2tf32(x.z);
        Qs[r * ATT_STRIDE + c + 3] = f2tf32(x.w);
    }

    float oacc[8][4];
#pragma unroll
    for (int di = 0; di < 8; di++)
#pragma unroll
        for (int i = 0; i < 4; i++) oacc[di][i] = 0.f;
    float m0 = -1e30f, m1 = -1e30f, l0 = 0.f, l1 = 0.f;

    const int r1 = qt * 64 + row_s + g;
    const int r2 = r1 + 8;

    for (int st = 0; st < 16; st++) {
        __syncthreads();   // protect Ks/Vts reuse vs previous PV mma

        // K tile -> Ks [s][d]
#pragma unroll
        for (int i = 0; i < 8; i++) {
            int v = tid + i * 128;
            int r = v >> 4;
            int c = (v & 15) * 4;
            float4 x = *(const float4*)(Kg + (size_t)(st * 64 + r) * HD + c);
            Ks[r * ATT_STRIDE + c + 0] = f2tf32(x.x);
            Ks[r * ATT_STRIDE + c + 1] = f2tf32(x.y);
            Ks[r * ATT_STRIDE + c + 2] = f2tf32(x.z);
            Ks[r * ATT_STRIDE + c + 3] = f2tf32(x.w);
        }
        // V tile -> Vts [d][s]  (lanes walk s => conflict-free smem stores)
#pragma unroll
        for (int i = 0; i < 8; i++) {
            int v  = tid + i * 128;
            int d4 = v >> 6;            // 0..15
            int s  = v & 63;
            float4 x = *(const float4*)(Vg + (size_t)(st * 64 + s) * HD + d4 * 4);
            Vts[(d4 * 4 + 0) * ATT_STRIDE + s] = f2tf32(x.x);
            Vts[(d4 * 4 + 1) * ATT_STRIDE + s] = f2tf32(x.y);
            Vts[(d4 * 4 + 2) * ATT_STRIDE + s] = f2tf32(x.z);
            Vts[(d4 * 4 + 3) * ATT_STRIDE + s] = f2tf32(x.w);
        }
        __syncthreads();

        // S = Q @ K^T for this warp's 16 rows x 64 s
        float sacc[8][4];
#pragma unroll
        for (int ni = 0; ni < 8; ni++)
#pragma unroll
            for (int i = 0; i < 4; i++) sacc[ni][i] = 0.f;

#pragma unroll
        for (int k0 = 0; k0 < 64; k0 += 8) {
            unsigned a[4];
            a[0] = Qs[(row_s + g) * ATT_STRIDE + k0 + t4];
            a[1] = Qs[(row_s + g + 8) * ATT_STRIDE + k0 + t4];
            a[2] = Qs[(row_s + g) * ATT_STRIDE + k0 + t4 + 4];
            a[3] = Qs[(row_s + g + 8) * ATT_STRIDE + k0 + t4 + 4];
#pragma unroll
            for (int ni = 0; ni < 8; ni++) {
                unsigned b0 = Ks[(ni * 8 + g) * ATT_STRIDE + k0 + t4];
                unsigned b1 = Ks[(ni * 8 + g) * ATT_STRIDE + k0 + t4 + 4];
                mma_tf32(sacc[ni], a, b0, b1);
            }
        }

        // + bias, tile row max
        float mx0 = -1e30f, mx1 = -1e30f;
        const float* bp1 = Bg + (size_t)r1 * T_DIM + st * 64;
        const float* bp2 = Bg + (size_t)r2 * T_DIM + st * 64;
#pragma unroll
        for (int ni = 0; ni < 8; ni++) {
            int cc = ni * 8 + t4 * 2;
            float2 z1 = *(const float2*)(bp1 + cc);
            float2 z2 = *(const float2*)(bp2 + cc);
            sacc[ni][0] += z1.x; sacc[ni][1] += z1.y;
            sacc[ni][2] += z2.x; sacc[ni][3] += z2.y;
            mx0 = fmaxf(mx0, fmaxf(sacc[ni][0], sacc[ni][1]));
            mx1 = fmaxf(mx1, fmaxf(sacc[ni][2], sacc[ni][3]));
        }
        mx0 = fmaxf(mx0, __shfl_xor_sync(0xffffffffu, mx0, 1));
        mx0 = fmaxf(mx0, __shfl_xor_sync(0xffffffffu, mx0, 2));
        mx1 = fmaxf(mx1, __shfl_xor_sync(0xffffffffu, mx1, 1));
        mx1 = fmaxf(mx1, __shfl_xor_sync(0xffffffffu, mx1, 2));

        float mn0 = fmaxf(m0, mx0), mn1 = fmaxf(m1, mx1);
        float sc0 = __expf(m0 - mn0), sc1 = __expf(m1 - mn1);
        m0 = mn0; m1 = mn1;

        float rs0 = 0.f, rs1 = 0.f;
#pragma unroll
        for (int ni = 0; ni < 8; ni++) {
            float p0 = __expf(sacc[ni][0] - mn0);
            float p1 = __expf(sacc[ni][1] - mn0);
            float p2 = __expf(sacc[ni][2] - mn1);
            float p3 = __expf(sacc[ni][3] - mn1);
            rs0 += p0 + p1;
            rs1 += p2 + p3;
            int cc = ni * 8 + t4 * 2;
            Ps[(row_s + g) * ATT_STRIDE + cc]         = f2tf32(p0);
            Ps[(row_s + g) * ATT_STRIDE + cc + 1]     = f2tf32(p1);
            Ps[(row_s + g + 8) * ATT_STRIDE + cc]     = f2tf32(p2);
            Ps[(row_s + g + 8) * ATT_STRIDE + cc + 1] = f2tf32(p3);
        }
        rs0 += __shfl_xor_sync(0xffffffffu, rs0, 1);
        rs0 += __shfl_xor_sync(0xffffffffu, rs0, 2);
        rs1 += __shfl_xor_sync(0xffffffffu, rs1, 1);
        rs1 += __shfl_xor_sync(0xffffffffu, rs1, 2);
        l0 = l0 * sc0 + rs0;
        l1 = l1 * sc1 + rs1;

#pragma unroll
        for (int di = 0; di < 8; di++) {
            oacc[di][0] *= sc0; oacc[di][1] *= sc0;
            oacc[di][2] *= sc1; oacc[di][3] *= sc1;
        }
        __syncwarp();   // Ps rows are warp-private; make stores visible to lanes

        // O += P @ V    (A = Ps rows of this warp, B = Vts)
#pragma unroll
        for (int k0 = 0; k0 < 64; k0 += 8) {
            unsigned a[4];
            a[0] = Ps[(row_s + g) * ATT_STRIDE + k0 + t4];
            a[1] = Ps[(row_s + g + 8) * ATT_STRIDE + k0 + t4];
            a[2] = Ps[(row_s + g) * ATT_STRIDE + k0 + t4 + 4];
            a[3] = Ps[(row_s + g + 8) * ATT_STRIDE + k0 + t4 + 4];
#pragma unroll
            for (int di = 0; di < 8; di++) {
                unsigned b0 = Vts[(di * 8 + g) * ATT_STRIDE + k0 + t4];
                unsigned b1 = Vts[(di * 8 + g) * ATT_STRIDE + k0 + t4 + 4];
                mma_tf32(oacc[di], a, b0, b1);
            }
        }
    }

    // finalize: O /= l ; write to g_attnout[t][b][h*64+d]
    const float inv0 = 1.f / l0;
    const float inv1 = 1.f / l1;
    const int b_idx = bh >> 3;
    const int h_idx = bh & 7;
    float* o1 = g_attnout + ((size_t)r1 * B_DIM + b_idx) * E_DIM + h_idx * HD;
    float* o2 = g_attnout + ((size_t)r2 * B_DIM + b_idx) * E_DIM + h_idx * HD;
#pragma unroll
    for (int di = 0; di < 8; di++) {
        int d = di * 8 + t4 * 2;
        *(float2*)(o1 + d) = make_float2(oacc[di][0] * inv0, oacc[di][1] * inv0);
        *(float2*)(o2 + d) = make_float2(oacc[di][2] * inv1, oacc[di][3] * inv1);
    }
}

// ---------------------------------------------------------------------------
// Launch
// ---------------------------------------------------------------------------
extern "C" void kernel_launch(void* const* d_in, const int* in_sizes, int n_in,
                              void* d_out, int out_size) {
    (void)in_sizes; (void)n_in; (void)out_size;
    const float* query = (const float*)d_in[0];
    const float* dist  = (const float*)d_in[1];
    const float* inW   = (const float*)d_in[2];
    const float* inB   = (const float*)d_in[3];
    const float* outW  = (const float*)d_in[4];
    const float* outB  = (const float*)d_in[5];
    float* out = (float*)d_out;

    // 1. dist -> per-head contiguous bias
    bias_transpose_kernel<<<dim3(4, 1024, 4), 256>>>(dist);

    // 2. QKV projection (scatter epilogue into g_q/g_k/g_v)
    gemm_tf32_kernel<<<dim3(24, 64), 128>>>(query, inW, inB, nullptr, 512, 0);

    // 3. fused attention
    cudaFuncSetAttribute(attn_kernel,
                         cudaFuncAttributeMaxDynamicSharedMemorySize,
                         ATT_SMEM_BYTES);
    attn_kernel<<<dim3(16, 32), 128, ATT_SMEM_BYTES>>>();

    // 4. output projection
    gemm_tf32_kernel<<<dim3(8, 64), 128>>>(nullptr, outW, outB, out, 512, 1);
}

// round 6
// speedup vs baseline: 1.2541x; 1.2541x over previous
#include <cuda_runtime.h>

// Problem constants
#define T_DIM 1024
#define B_DIM 4
#define E_DIM 512
#define H_DIM 8
#define HD    64
#define BH    32          // B*H
#define M_ROWS 4096       // T*B

// ---------------------------------------------------------------------------
// Scratch (device globals; no allocations allowed in kernel_launch)
// ---------------------------------------------------------------------------
__device__ float g_q[BH * T_DIM * HD];        // 8 MB  (scaled by 1/8)
__device__ float g_k[BH * T_DIM * HD];        // 8 MB
__device__ float g_vt[BH * HD * T_DIM];       // 8 MB  V transposed: [bh][d][t]
__device__ float g_attnout[M_ROWS * E_DIM];   // 8 MB  ([T,B,E] layout)
__device__ float g_bias[BH * T_DIM * T_DIM];  // 134 MB (transposed dist)

// ---------------------------------------------------------------------------
// Helpers
// ---------------------------------------------------------------------------
__device__ __forceinline__ unsigned f2tf32(float x) {
    unsigned y;
    asm("cvt.rna.tf32.f32 %0, %1;" : "=r"(y) : "f"(x));
    return y;
}

__device__ __forceinline__ void mma_tf32(float c[4], const unsigned a[4],
                                         unsigned b0, unsigned b1) {
    asm volatile(
        "mma.sync.aligned.m16n8k8.row.col.f32.tf32.tf32.f32 "
        "{%0,%1,%2,%3}, {%4,%5,%6,%7}, {%8,%9}, {%0,%1,%2,%3};\n"
        : "+f"(c[0]), "+f"(c[1]), "+f"(c[2]), "+f"(c[3])
        : "r"(a[0]), "r"(a[1]), "r"(a[2]), "r"(a[3]), "r"(b0), "r"(b1));
}

// ---------------------------------------------------------------------------
// Kernel 1: dist [B,T,T,H] -> g_bias [B*H, T, T]   (fully coalesced both sides)
// ---------------------------------------------------------------------------
__global__ void bias_transpose_kernel(const float* __restrict__ dist) {
    __shared__ float sm[H_DIM][264];
    const int sc  = blockIdx.x;        // s chunk: 0..3 (256 each)
    const int t   = blockIdx.y;        // 0..1023
    const int b   = blockIdx.z;        // 0..3
    const int tid = threadIdx.x;       // 256 threads

    const float* src = dist + (((size_t)(b * T_DIM + t)) * T_DIM + sc * 256) * H_DIM;
    float4 v0 = *(const float4*)(src + (size_t)tid * 8);
    float4 v1 = *(const float4*)(src + (size_t)tid * 8 + 4);
    sm[0][tid] = v0.x; sm[1][tid] = v0.y; sm[2][tid] = v0.z; sm[3][tid] = v0.w;
    sm[4][tid] = v1.x; sm[5][tid] = v1.y; sm[6][tid] = v1.z; sm[7][tid] = v1.w;
    __syncthreads();

#pragma unroll
    for (int h = 0; h < H_DIM; h++) {
        size_t dst = (((size_t)(b * H_DIM + h) * T_DIM + t) * T_DIM) + sc * 256 + tid;
        g_bias[dst] = sm[h][tid];
    }
}

// ---------------------------------------------------------------------------
// Kernel 2/4: tf32 GEMM  C[M,N] = A[M,K] @ W[N,K]^T + bias
// ---------------------------------------------------------------------------
__device__ __forceinline__ void qkv_store(int m, int n, float val,
                                          const float* __restrict__ bias) {
    val += bias[n];
    const int sec = n >> 9;      // 0:q 1:k 2:v
    const int e   = n & 511;
    const int h   = e >> 6;
    const int d   = e & 63;
    const int tt  = m >> 2;      // token (m = t*4 + b)
    const int bb  = m & 3;
    if (sec == 0) {
        g_q[((((bb << 3) + h) << 10) + tt) * 64 + d] = val * 0.125f;  // 1/sqrt(64)
    } else if (sec == 1) {
        g_k[((((bb << 3) + h) << 10) + tt) * 64 + d] = val;
    } else {
        // V transposed: [bh][d][t]
        g_vt[((((bb << 3) + h) << 6) + d) * 1024 + tt] = val;
    }
}

__global__ void gemm_tf32_kernel(const float* __restrict__ A_in,
                                 const float* __restrict__ W,
                                 const float* __restrict__ bias,
                                 float* __restrict__ Cout,
                                 int K, int mode) {
    __shared__ unsigned As[64 * 20];
    __shared__ unsigned Bs[64 * 20];

    const float* __restrict__ A = (mode == 0) ? A_in : g_attnout;

    const int tid  = threadIdx.x;
    const int lane = tid & 31;
    const int w    = tid >> 5;
    const int g    = lane >> 2;
    const int t4   = lane & 3;
    const int wm   = (w >> 1) * 32;
    const int wn   = (w & 1) * 32;
    const int bm0  = blockIdx.y * 64;
    const int bn0  = blockIdx.x * 64;

    float acc[2][4][4];
#pragma unroll
    for (int mi = 0; mi < 2; mi++)
#pragma unroll
        for (int ni = 0; ni < 4; ni++)
#pragma unroll
            for (int i = 0; i < 4; i++) acc[mi][ni][i] = 0.f;

    const int nkt = K >> 4;
    for (int kt = 0; kt < nkt; kt++) {
#pragma unroll
        for (int i = 0; i < 2; i++) {
            int v = tid + i * 128;
            int r = v >> 2;
            int c = (v & 3) * 4;
            float4 xa = *(const float4*)(A + (size_t)(bm0 + r) * K + kt * 16 + c);
            As[r * 20 + c + 0] = f2tf32(xa.x);
            As[r * 20 + c + 1] = f2tf32(xa.y);
            As[r * 20 + c + 2] = f2tf32(xa.z);
            As[r * 20 + c + 3] = f2tf32(xa.w);
            float4 xb = *(const float4*)(W + (size_t)(bn0 + r) * K + kt * 16 + c);
            Bs[r * 20 + c + 0] = f2tf32(xb.x);
            Bs[r * 20 + c + 1] = f2tf32(xb.y);
            Bs[r * 20 + c + 2] = f2tf32(xb.z);
            Bs[r * 20 + c + 3] = f2tf32(xb.w);
        }
        __syncthreads();

#pragma unroll
        for (int ks = 0; ks < 2; ks++) {
            const int k0 = ks * 8;
            unsigned a[2][4], bf[4][2];
#pragma unroll
            for (int mi = 0; mi < 2; mi++) {
                int r = wm + mi * 16 + g;
                a[mi][0] = As[r * 20 + k0 + t4];
                a[mi][1] = As[(r + 8) * 20 + k0 + t4];
                a[mi][2] = As[r * 20 + k0 + t4 + 4];
                a[mi][3] = As[(r + 8) * 20 + k0 + t4 + 4];
            }
#pragma unroll
            for (int ni = 0; ni < 4; ni++) {
                int n = wn + ni * 8 + g;
                bf[ni][0] = Bs[n * 20 + k0 + t4];
                bf[ni][1] = Bs[n * 20 + k0 + t4 + 4];
            }
#pragma unroll
            for (int mi = 0; mi < 2; mi++)
#pragma unroll
                for (int ni = 0; ni < 4; ni++)
                    mma_tf32(acc[mi][ni], a[mi], bf[ni][0], bf[ni][1]);
        }
        __syncthreads();
    }

#pragma unroll
    for (int mi = 0; mi < 2; mi++) {
#pragma unroll
        for (int ni = 0; ni < 4; ni++) {
            int m = bm0 + wm + mi * 16 + g;
            int n = bn0 + wn + ni * 8 + t4 * 2;
            if (mode == 0) {
                qkv_store(m,     n,     acc[mi][ni][0], bias);
                qkv_store(m,     n + 1, acc[mi][ni][1], bias);
                qkv_store(m + 8, n,     acc[mi][ni][2], bias);
                qkv_store(m + 8, n + 1, acc[mi][ni][3], bias);
            } else {
                Cout[(size_t)m * 512 + n]           = acc[mi][ni][0] + bias[n];
                Cout[(size_t)m * 512 + n + 1]       = acc[mi][ni][1] + bias[n + 1];
                Cout[(size_t)(m + 8) * 512 + n]     = acc[mi][ni][2] + bias[n];
                Cout[(size_t)(m + 8) * 512 + n + 1] = acc[mi][ni][3] + bias[n + 1];
            }
        }
    }
}

// ---------------------------------------------------------------------------
// Kernel 3: fused flash attention, tf32 mma
//   grid (8 q-tiles of 128 rows, 32 heads); 256 threads = 8 warps,
//   warp w owns rows w*16..w*16+15. Online softmax over 16 s-tiles of 64.
//   P relayout (C-frag -> A-frag) done with in-quad SHFL (no smem round-trip).
// ---------------------------------------------------------------------------
#define AS 68            // 68 mod 32 == 4 -> conflict-free fragment access
#define BSS 72           // bias smem stride: 72 -> conflict-free float2 frag reads
#define OFF_Q 0
#define OFF_K (128 * AS)
#define OFF_V (OFF_K + 64 * AS)
#define OFF_B (OFF_V + 64 * AS)
#define ATT_WORDS (OFF_B + 128 * BSS)
#define ATT_BYTES (ATT_WORDS * 4)

__global__ void __launch_bounds__(256, 2) attn_kernel() {
    extern __shared__ unsigned smem[];
    unsigned* Qs  = smem + OFF_Q;    // [128][68] tf32
    unsigned* Ks  = smem + OFF_K;    // [64][68]  tf32  rows=s cols=d
    unsigned* Vts = smem + OFF_V;    // [64][68]  tf32  rows=d cols=s
    float*    Bsm = (float*)(smem + OFF_B);  // [128][72] raw fp32 bias tile

    const int qt   = blockIdx.x;   // 0..7
    const int bh   = blockIdx.y;   // 0..31
    const int tid  = threadIdx.x;
    const int lane = tid & 31;
    const int w    = tid >> 5;
    const int g    = lane >> 2;
    const int t4   = lane & 3;
    const int row_s = w * 16;
    const int r1l = row_s + g;
    const int r2l = r1l + 8;
    const int src0 = (g << 2) + (t4 >> 1);
    const int src2 = src0 + 2;
    const bool odd = (t4 & 1);

    const float* __restrict__ Qg  = g_q  + ((size_t)bh * T_DIM + qt * 128) * HD;
    const float* __restrict__ Kg  = g_k  + (size_t)bh * T_DIM * HD;
    const float* __restrict__ Vtg = g_vt + (size_t)bh * HD * T_DIM;
    const float* __restrict__ Bg  = g_bias + ((size_t)bh * T_DIM + qt * 128) * T_DIM;

    // load Q tile (128x64) -> Qs
#pragma unroll
    for (int i = 0; i < 8; i++) {
        int v = tid + i * 256;
        int r = v >> 4;
        int c = (v & 15) * 4;
        float4 x = *(const float4*)(Qg + (size_t)r * HD + c);
        Qs[r * AS + c + 0] = f2tf32(x.x);
        Qs[r * AS + c + 1] = f2tf32(x.y);
        Qs[r * AS + c + 2] = f2tf32(x.z);
        Qs[r * AS + c + 3] = f2tf32(x.w);
    }

    float oacc[8][4];
#pragma unroll
    for (int di = 0; di < 8; di++)
#pragma unroll
        for (int i = 0; i < 4; i++) oacc[di][i] = 0.f;
    float m0 = -1e30f, m1 = -1e30f, l0 = 0.f, l1 = 0.f;

    for (int st = 0; st < 16; st++) {
        __syncthreads();   // all warps done with previous Ks/Vts/Bsm

        // K tile -> Ks [s][d]   (coalesced)
#pragma unroll
        for (int i = 0; i < 4; i++) {
            int v = tid + i * 256;
            int r = v >> 4;
            int c = (v & 15) * 4;
            float4 x = *(const float4*)(Kg + (size_t)(st * 64 + r) * HD + c);
            Ks[r * AS + c + 0] = f2tf32(x.x);
            Ks[r * AS + c + 1] = f2tf32(x.y);
            Ks[r * AS + c + 2] = f2tf32(x.z);
            Ks[r * AS + c + 3] = f2tf32(x.w);
        }
        // V^T tile -> Vts [d][s]  (coalesced: g_vt is [d][t])
#pragma unroll
        for (int i = 0; i < 4; i++) {
            int v = tid + i * 256;
            int r = v >> 4;             // d row
            int c = (v & 15) * 4;       // s offset
            float4 x = *(const float4*)(Vtg + (size_t)r * T_DIM + st * 64 + c);
            Vts[r * AS + c + 0] = f2tf32(x.x);
            Vts[r * AS + c + 1] = f2tf32(x.y);
            Vts[r * AS + c + 2] = f2tf32(x.z);
            Vts[r * AS + c + 3] = f2tf32(x.w);
        }
        // bias tile (128 x 64) -> Bsm   (coalesced float4)
#pragma unroll
        for (int i = 0; i < 8; i++) {
            int v = tid + i * 256;
            int r = v >> 4;
            int c = (v & 15) * 4;
            float4 x = *(const float4*)(Bg + (size_t)r * T_DIM + st * 64 + c);
            *(float4*)(Bsm + r * BSS + c) = x;
        }
        __syncthreads();

        // S = Q @ K^T for this warp's 16 rows x 64 s
        float sacc[8][4];
#pragma unroll
        for (int ni = 0; ni < 8; ni++)
#pragma unroll
            for (int i = 0; i < 4; i++) sacc[ni][i] = 0.f;

#pragma unroll
        for (int k0 = 0; k0 < 64; k0 += 8) {
            unsigned a[4];
            a[0] = Qs[r1l * AS + k0 + t4];
            a[1] = Qs[r2l * AS + k0 + t4];
            a[2] = Qs[r1l * AS + k0 + t4 + 4];
            a[3] = Qs[r2l * AS + k0 + t4 + 4];
#pragma unroll
            for (int ni = 0; ni < 8; ni++) {
                unsigned b0 = Ks[(ni * 8 + g) * AS + k0 + t4];
                unsigned b1 = Ks[(ni * 8 + g) * AS + k0 + t4 + 4];
                mma_tf32(sacc[ni], a, b0, b1);
            }
        }

        // + bias (from smem), row max
        float mx0 = -1e30f, mx1 = -1e30f;
#pragma unroll
        for (int ni = 0; ni < 8; ni++) {
            int cc = ni * 8 + t4 * 2;
            float2 z1 = *(const float2*)(Bsm + r1l * BSS + cc);
            float2 z2 = *(const float2*)(Bsm + r2l * BSS + cc);
            sacc[ni][0] += z1.x; sacc[ni][1] += z1.y;
            sacc[ni][2] += z2.x; sacc[ni][3] += z2.y;
            mx0 = fmaxf(mx0, fmaxf(sacc[ni][0], sacc[ni][1]));
            mx1 = fmaxf(mx1, fmaxf(sacc[ni][2], sacc[ni][3]));
        }
        mx0 = fmaxf(mx0, __shfl_xor_sync(0xffffffffu, mx0, 1));
        mx0 = fmaxf(mx0, __shfl_xor_sync(0xffffffffu, mx0, 2));
        mx1 = fmaxf(mx1, __shfl_xor_sync(0xffffffffu, mx1, 1));
        mx1 = fmaxf(mx1, __shfl_xor_sync(0xffffffffu, mx1, 2));

        float mn0 = fmaxf(m0, mx0), mn1 = fmaxf(m1, mx1);
        float sc0 = __expf(m0 - mn0), sc1 = __expf(m1 - mn1);
        m0 = mn0; m1 = mn1;

        float rs0 = 0.f, rs1 = 0.f;
#pragma unroll
        for (int ni = 0; ni < 8; ni++) {
            float p0 = __expf(sacc[ni][0] - mn0);
            float p1 = __expf(sacc[ni][1] - mn0);
            float p2 = __expf(sacc[ni][2] - mn1);
            float p3 = __expf(sacc[ni][3] - mn1);
            rs0 += p0 + p1;
            rs1 += p2 + p3;
            sacc[ni][0] = p0; sacc[ni][1] = p1;
            sacc[ni][2] = p2; sacc[ni][3] = p3;
        }
        rs0 += __shfl_xor_sync(0xffffffffu, rs0, 1);
        rs0 += __shfl_xor_sync(0xffffffffu, rs0, 2);
        rs1 += __shfl_xor_sync(0xffffffffu, rs1, 1);
        rs1 += __shfl_xor_sync(0xffffffffu, rs1, 2);
        l0 = l0 * sc0 + rs0;
        l1 = l1 * sc1 + rs1;

#pragma unroll
        for (int di = 0; di < 8; di++) {
            oacc[di][0] *= sc0; oacc[di][1] *= sc0;
            oacc[di][2] *= sc1; oacc[di][3] *= sc1;
        }

        // O += P @ V : relayout P C-frag -> A-frag via in-quad shuffles
#pragma unroll
        for (int ni = 0; ni < 8; ni++) {
            float s0 = __shfl_sync(0xffffffffu, sacc[ni][0], src0);
            float s1 = __shfl_sync(0xffffffffu, sacc[ni][1], src0);
            float s2 = __shfl_sync(0xffffffffu, sacc[ni][2], src0);
            float s3 = __shfl_sync(0xffffffffu, sacc[ni][3], src0);
            float u0 = __shfl_sync(0xffffffffu, sacc[ni][0], src2);
            float u1 = __shfl_sync(0xffffffffu, sacc[ni][1], src2);
            float u2 = __shfl_sync(0xffffffffu, sacc[ni][2], src2);
            float u3 = __shfl_sync(0xffffffffu, sacc[ni][3], src2);
            unsigned a[4];
            a[0] = f2tf32(odd ? s1 : s0);
            a[1] = f2tf32(odd ? s3 : s2);
            a[2] = f2tf32(odd ? u1 : u0);
            a[3] = f2tf32(odd ? u3 : u2);
            const int k0 = ni * 8;
#pragma unroll
            for (int di = 0; di < 8; di++) {
                unsigned b0 = Vts[(di * 8 + g) * AS + k0 + t4];
                unsigned b1 = Vts[(di * 8 + g) * AS + k0 + t4 + 4];
                mma_tf32(oacc[di], a, b0, b1);
            }
        }
    }

    // finalize: O /= l ; write to g_attnout[t][b][h*64+d]
    const float inv0 = 1.f / l0;
    const float inv1 = 1.f / l1;
    const int b_idx = bh >> 3;
    const int h_idx = bh & 7;
    const int q1 = qt * 128 + r1l;
    const int q2 = q1 + 8;
    float* o1 = g_attnout + ((size_t)q1 * B_DIM + b_idx) * E_DIM + h_idx * HD;
    float* o2 = g_attnout + ((size_t)q2 * B_DIM + b_idx) * E_DIM + h_idx * HD;
#pragma unroll
    for (int di = 0; di < 8; di++) {
        int d = di * 8 + t4 * 2;
        *(float2*)(o1 + d) = make_float2(oacc[di][0] * inv0, oacc[di][1] * inv0);
        *(float2*)(o2 + d) = make_float2(oacc[di][2] * inv1, oacc[di][3] * inv1);
    }
}

// ---------------------------------------------------------------------------
// Launch
// ---------------------------------------------------------------------------
extern "C" void kernel_launch(void* const* d_in, const int* in_sizes, int n_in,
                              void* d_out, int out_size) {
    (void)in_sizes; (void)n_in; (void)out_size;
    const float* query = (const float*)d_in[0];
    const float* dist  = (const float*)d_in[1];
    const float* inW   = (const float*)d_in[2];
    const float* inB   = (const float*)d_in[3];
    const float* outW  = (const float*)d_in[4];
    const float* outB  = (const float*)d_in[5];
    float* out = (float*)d_out;

    // 1. dist -> per-head contiguous bias
    bias_transpose_kernel<<<dim3(4, 1024, 4), 256>>>(dist);

    // 2. QKV projection (scatter epilogue into g_q/g_k/g_vt)
    gemm_tf32_kernel<<<dim3(24, 64), 128>>>(query, inW, inB, nullptr, 512, 0);

    // 3. fused attention
    cudaFuncSetAttribute(attn_kernel,
                         cudaFuncAttributeMaxDynamicSharedMemorySize,
                         ATT_BYTES);
    attn_kernel<<<dim3(8, 32), 256, ATT_BYTES>>>();

    // 4. output projection
    gemm_tf32_kernel<<<dim3(8, 64), 128>>>(nullptr, outW, outB, out, 512, 1);
}

// round 7
// speedup vs baseline: 1.9791x; 1.5782x over previous
#include <cuda_runtime.h>
#include <cuda_fp16.h>

// Problem constants
#define T_DIM 1024
#define B_DIM 4
#define E_DIM 512
#define H_DIM 8
#define HD    64
#define BH    32
#define M_ROWS 4096

// ---------------------------------------------------------------------------
// Scratch (fp16 everywhere; fp32 accumulation in mma)
// ---------------------------------------------------------------------------
__device__ __half g_qh[BH * T_DIM * HD];          // 4 MB, scaled by 1/8
__device__ __half g_kh[BH * T_DIM * HD];          // 4 MB
__device__ __half g_vth[BH * HD * T_DIM];         // 4 MB, V^T: [bh][d][t]
__device__ __half g_ao[M_ROWS * E_DIM];           // 4 MB, [t*4+b][e]
__device__ __half g_biash[(size_t)BH * T_DIM * T_DIM];  // 67 MB

// 128B-row swizzle (Swizzle<3,4,3>): conflict-free ldmatrix + linear fills
__device__ __forceinline__ int SWZ(int b) { return b ^ ((b >> 3) & 0x70); }

__device__ __forceinline__ void ldmx4(unsigned r[4], const void* p) {
    unsigned addr = (unsigned)__cvta_generic_to_shared(p);
    asm volatile("ldmatrix.sync.aligned.m8n8.x4.shared.b16 {%0,%1,%2,%3},[%4];"
                 : "=r"(r[0]), "=r"(r[1]), "=r"(r[2]), "=r"(r[3]) : "r"(addr));
}

__device__ __forceinline__ void mma16(float c[4], const unsigned a[4],
                                      unsigned b0, unsigned b1) {
    asm volatile(
        "mma.sync.aligned.m16n8k16.row.col.f32.f16.f16.f32 "
        "{%0,%1,%2,%3},{%4,%5,%6,%7},{%8,%9},{%0,%1,%2,%3};"
        : "+f"(c[0]), "+f"(c[1]), "+f"(c[2]), "+f"(c[3])
        : "r"(a[0]), "r"(a[1]), "r"(a[2]), "r"(a[3]), "r"(b0), "r"(b1));
}

// ---------------------------------------------------------------------------
// Kernel 1: dist [B,T,T,H] fp32 -> g_biash [B*H,T,T] fp16 (no smem needed:
// each thread owns 2 consecutive s for all 8 h -> half2 stores are coalesced)
// ---------------------------------------------------------------------------
__global__ void bias_transpose_kernel(const float* __restrict__ dist) {
    const int t = blockIdx.x;
    const int b = blockIdx.y;
    const int tid = threadIdx.x;   // 512 threads; s0 = 2*tid
    const float* src = dist + ((size_t)(b * T_DIM + t) * T_DIM + tid * 2) * H_DIM;
    float4 a0 = *(const float4*)(src);
    float4 a1 = *(const float4*)(src + 4);
    float4 b0 = *(const float4*)(src + 8);
    float4 b1 = *(const float4*)(src + 12);
    __half* dst = g_biash + (size_t)b * H_DIM * T_DIM * T_DIM
                + (size_t)t * T_DIM + tid * 2;
    const size_t hs = (size_t)T_DIM * T_DIM;
    *(half2*)(dst + 0 * hs) = __floats2half2_rn(a0.x, b0.x);
    *(half2*)(dst + 1 * hs) = __floats2half2_rn(a0.y, b0.y);
    *(half2*)(dst + 2 * hs) = __floats2half2_rn(a0.z, b0.z);
    *(half2*)(dst + 3 * hs) = __floats2half2_rn(a0.w, b0.w);
    *(half2*)(dst + 4 * hs) = __floats2half2_rn(a1.x, b1.x);
    *(half2*)(dst + 5 * hs) = __floats2half2_rn(a1.y, b1.y);
    *(half2*)(dst + 6 * hs) = __floats2half2_rn(a1.z, b1.z);
    *(half2*)(dst + 7 * hs) = __floats2half2_rn(a1.w, b1.w);
}

// ---------------------------------------------------------------------------
// Kernel 2/4: fp16 GEMM  C[M,N] = A[M,512] @ W[N,512]^T + bias
//   64x64 tile, BK=64, 128 threads (4 warps 2x2, warp tile 32x32), ldmatrix.
//   mode 0: A = query (fp32, convert), epilogue -> g_qh/g_kh/g_vth
//   mode 1: A = g_ao (fp16),           epilogue -> Cout fp32 + bias
// ---------------------------------------------------------------------------
__device__ __forceinline__ void qkv_store2(int m, int n, float v0, float v1,
                                           const float* __restrict__ bias) {
    v0 += bias[n]; v1 += bias[n + 1];
    const int sec = n >> 9;
    const int e   = n & 511;
    const int h   = e >> 6;
    const int d   = e & 63;
    const int tt  = m >> 2;
    const int bb  = m & 3;
    const int bh  = bb * 8 + h;
    if (sec == 0) {
        *(half2*)&g_qh[((size_t)bh * 1024 + tt) * 64 + d] =
            __floats2half2_rn(v0 * 0.125f, v1 * 0.125f);
    } else if (sec == 1) {
        *(half2*)&g_kh[((size_t)bh * 1024 + tt) * 64 + d] =
            __floats2half2_rn(v0, v1);
    } else {
        g_vth[((size_t)bh * 64 + d) * 1024 + tt]     = __float2half_rn(v0);
        g_vth[((size_t)bh * 64 + d + 1) * 1024 + tt] = __float2half_rn(v1);
    }
}

__global__ void __launch_bounds__(128) gemm_f16_kernel(
    const float* __restrict__ A32, const float* __restrict__ W,
    const float* __restrict__ bias, float* __restrict__ Cout, int mode) {
    __shared__ __align__(1024) __half As[64 * 64];
    __shared__ __align__(1024) __half Bs[64 * 64];

    const int tid  = threadIdx.x;
    const int lane = tid & 31;
    const int w    = tid >> 5;
    const int g    = lane >> 2;
    const int t4   = lane & 3;
    const int wm   = (w >> 1) * 32;
    const int wn   = (w & 1) * 32;
    const int bm0  = blockIdx.y * 64;
    const int bn0  = blockIdx.x * 64;
    const int K    = 512;

    const int arow = (lane & 7) + ((lane >> 3) & 1) * 8;
    const int acol = ((lane >> 4) & 1) * 8;
    const int brow = (lane & 7) + ((lane >> 4) & 1) * 8;
    const int bcol = ((lane >> 3) & 1) * 8;

    float acc[2][4][4];
#pragma unroll
    for (int mi = 0; mi < 2; mi++)
#pragma unroll
        for (int ni = 0; ni < 4; ni++)
#pragma unroll
            for (int i = 0; i < 4; i++) acc[mi][ni][i] = 0.f;

    for (int kt = 0; kt < 8; kt++) {
        if (mode == 0) {
#pragma unroll
            for (int i = 0; i < 8; i++) {
                int idx = tid + i * 128;
                int r = idx >> 4, c = (idx & 15) * 4;
                float4 x = *(const float4*)(A32 + (size_t)(bm0 + r) * K + kt * 64 + c);
                char* p = (char*)As + SWZ(r * 128 + c * 2);
                *(half2*)p       = __floats2half2_rn(x.x, x.y);
                *(half2*)(p + 4) = __floats2half2_rn(x.z, x.w);
            }
        } else {
#pragma unroll
            for (int i = 0; i < 4; i++) {
                int idx = tid + i * 128;
                int r = idx >> 3, c8 = (idx & 7) * 8;
                uint4 x = *(const uint4*)(g_ao + (size_t)(bm0 + r) * K + kt * 64 + c8);
                *(uint4*)((char*)As + SWZ(r * 128 + c8 * 2)) = x;
            }
        }
#pragma unroll
        for (int i = 0; i < 8; i++) {
            int idx = tid + i * 128;
            int r = idx >> 4, c = (idx & 15) * 4;
            float4 x = *(const float4*)(W + (size_t)(bn0 + r) * K + kt * 64 + c);
            char* p = (char*)Bs + SWZ(r * 128 + c * 2);
            *(half2*)p       = __floats2half2_rn(x.x, x.y);
            *(half2*)(p + 4) = __floats2half2_rn(x.z, x.w);
        }
        __syncthreads();

#pragma unroll
        for (int kb = 0; kb < 4; kb++) {
            unsigned a[2][4];
#pragma unroll
            for (int mi = 0; mi < 2; mi++)
                ldmx4(a[mi], (char*)As + SWZ((wm + mi * 16 + arow) * 128 + (kb * 16 + acol) * 2));
#pragma unroll
            for (int nip = 0; nip < 2; nip++) {
                unsigned bf[4];
                ldmx4(bf, (char*)Bs + SWZ((wn + nip * 16 + brow) * 128 + (kb * 16 + bcol) * 2));
#pragma unroll
                for (int mi = 0; mi < 2; mi++) {
                    mma16(acc[mi][nip * 2],     a[mi], bf[0], bf[1]);
                    mma16(acc[mi][nip * 2 + 1], a[mi], bf[2], bf[3]);
                }
            }
        }
        __syncthreads();
    }

#pragma unroll
    for (int mi = 0; mi < 2; mi++) {
#pragma unroll
        for (int ni = 0; ni < 4; ni++) {
            int m = bm0 + wm + mi * 16 + g;
            int n = bn0 + wn + ni * 8 + t4 * 2;
            if (mode == 0) {
                qkv_store2(m,     n, acc[mi][ni][0], acc[mi][ni][1], bias);
                qkv_store2(m + 8, n, acc[mi][ni][2], acc[mi][ni][3], bias);
            } else {
                *(float2*)&Cout[(size_t)m * 512 + n] =
                    make_float2(acc[mi][ni][0] + bias[n], acc[mi][ni][1] + bias[n + 1]);
                *(float2*)&Cout[(size_t)(m + 8) * 512 + n] =
                    make_float2(acc[mi][ni][2] + bias[n], acc[mi][ni][3] + bias[n + 1]);
            }
        }
    }
}

// ---------------------------------------------------------------------------
// Kernel 3: fused flash attention, fp16 mma + ldmatrix
//   grid (16 q-tiles of 64 rows, 32 heads); 128 threads = 4 warps,
//   warp w owns q-rows w*16..w*16+15. s-tiles of 64, online softmax.
// ---------------------------------------------------------------------------
__global__ void __launch_bounds__(128, 4) attn_kernel() {
    __shared__ __align__(1024) __half Qs[64 * 64];
    __shared__ __align__(1024) __half Ks[64 * 64];
    __shared__ __align__(1024) __half Vts[64 * 64];
    __shared__ __align__(1024) __half Bsm[64 * 64];
    __shared__ __align__(1024) __half Ps[64 * 64];

    const int qt   = blockIdx.x;   // 0..15
    const int bh   = blockIdx.y;   // 0..31
    const int tid  = threadIdx.x;
    const int lane = tid & 31;
    const int w    = tid >> 5;
    const int g    = lane >> 2;
    const int t4   = lane & 3;
    const int row_s = w * 16;
    const int arow = (lane & 7) + ((lane >> 3) & 1) * 8;
    const int acol = ((lane >> 4) & 1) * 8;
    const int brow = (lane & 7) + ((lane >> 4) & 1) * 8;
    const int bcol = ((lane >> 3) & 1) * 8;

    const __half* __restrict__ Qg = g_qh + ((size_t)bh * 1024 + qt * 64) * 64;
    const __half* __restrict__ Kg = g_kh + (size_t)bh * 1024 * 64;
    const __half* __restrict__ Vg = g_vth + (size_t)bh * 64 * 1024;
    const __half* __restrict__ Bg = g_biash + ((size_t)bh * 1024 + qt * 64) * 1024;

    // Q tile -> Qs
#pragma unroll
    for (int i = 0; i < 4; i++) {
        int idx = tid + i * 128;
        int r = idx >> 3, c8 = (idx & 7) * 8;
        *(uint4*)((char*)Qs + SWZ(r * 128 + c8 * 2)) = *(const uint4*)(Qg + r * 64 + c8);
    }

    float oacc[8][4];
#pragma unroll
    for (int di = 0; di < 8; di++)
#pragma unroll
        for (int i = 0; i < 4; i++) oacc[di][i] = 0.f;
    float m0 = -1e30f, m1 = -1e30f, l0 = 0.f, l1 = 0.f;

    for (int st = 0; st < 16; st++) {
        __syncthreads();
#pragma unroll
        for (int i = 0; i < 4; i++) {
            int idx = tid + i * 128;
            int r = idx >> 3, c8 = (idx & 7) * 8;
            *(uint4*)((char*)Ks + SWZ(r * 128 + c8 * 2)) =
                *(const uint4*)(Kg + (size_t)(st * 64 + r) * 64 + c8);
            *(uint4*)((char*)Vts + SWZ(r * 128 + c8 * 2)) =
                *(const uint4*)(Vg + (size_t)r * 1024 + st * 64 + c8);
            *(uint4*)((char*)Bsm + SWZ(r * 128 + c8 * 2)) =
                *(const uint4*)(Bg + (size_t)r * 1024 + st * 64 + c8);
        }
        __syncthreads();

        // S = Q K^T  (warp: 16 q-rows x 64 s)
        float sacc[8][4];
#pragma unroll
        for (int ni = 0; ni < 8; ni++)
#pragma unroll
            for (int i = 0; i < 4; i++) sacc[ni][i] = 0.f;

#pragma unroll
        for (int kb = 0; kb < 4; kb++) {
            unsigned a[4];
            ldmx4(a, (char*)Qs + SWZ((row_s + arow) * 128 + (kb * 16 + acol) * 2));
#pragma unroll
            for (int nip = 0; nip < 4; nip++) {
                unsigned bf[4];
                ldmx4(bf, (char*)Ks + SWZ((nip * 16 + brow) * 128 + (kb * 16 + bcol) * 2));
                mma16(sacc[nip * 2],     a, bf[0], bf[1]);
                mma16(sacc[nip * 2 + 1], a, bf[2], bf[3]);
            }
        }

        // + bias (fp16 smem), row max
        float mx0 = -1e30f, mx1 = -1e30f;
#pragma unroll
        for (int ni = 0; ni < 8; ni++) {
            half2 u1 = *(const half2*)((const char*)Bsm +
                          SWZ((row_s + g) * 128 + (ni * 8 + 2 * t4) * 2));
            half2 u2 = *(const half2*)((const char*)Bsm +
                          SWZ((row_s + g + 8) * 128 + (ni * 8 + 2 * t4) * 2));
            float2 z1 = __half22float2(u1);
            float2 z2 = __half22float2(u2);
            sacc[ni][0] += z1.x; sacc[ni][1] += z1.y;
            sacc[ni][2] += z2.x; sacc[ni][3] += z2.y;
            mx0 = fmaxf(mx0, fmaxf(sacc[ni][0], sacc[ni][1]));
            mx1 = fmaxf(mx1, fmaxf(sacc[ni][2], sacc[ni][3]));
        }
        mx0 = fmaxf(mx0, __shfl_xor_sync(0xffffffffu, mx0, 1));
        mx0 = fmaxf(mx0, __shfl_xor_sync(0xffffffffu, mx0, 2));
        mx1 = fmaxf(mx1, __shfl_xor_sync(0xffffffffu, mx1, 1));
        mx1 = fmaxf(mx1, __shfl_xor_sync(0xffffffffu, mx1, 2));

        float mn0 = fmaxf(m0, mx0), mn1 = fmaxf(m1, mx1);
        float sc0 = __expf(m0 - mn0), sc1 = __expf(m1 - mn1);
        m0 = mn0; m1 = mn1;

        float rs0 = 0.f, rs1 = 0.f;
#pragma unroll
        for (int ni = 0; ni < 8; ni++) {
            sacc[ni][0] = __expf(sacc[ni][0] - mn0);
            sacc[ni][1] = __expf(sacc[ni][1] - mn0);
            sacc[ni][2] = __expf(sacc[ni][2] - mn1);
            sacc[ni][3] = __expf(sacc[ni][3] - mn1);
            rs0 += sacc[ni][0] + sacc[ni][1];
            rs1 += sacc[ni][2] + sacc[ni][3];
        }
        rs0 += __shfl_xor_sync(0xffffffffu, rs0, 1);
        rs0 += __shfl_xor_sync(0xffffffffu, rs0, 2);
        rs1 += __shfl_xor_sync(0xffffffffu, rs1, 1);
        rs1 += __shfl_xor_sync(0xffffffffu, rs1, 2);
        l0 = l0 * sc0 + rs0;
        l1 = l1 * sc1 + rs1;

#pragma unroll
        for (int di = 0; di < 8; di++) {
            oacc[di][0] *= sc0; oacc[di][1] *= sc0;
            oacc[di][2] *= sc1; oacc[di][3] *= sc1;
        }

        // P -> smem fp16 (warp-private rows), then PV via ldmatrix
        __syncwarp();
#pragma unroll
        for (int ni = 0; ni < 8; ni++) {
            *(half2*)((char*)Ps + SWZ((row_s + g) * 128 + (ni * 8 + 2 * t4) * 2)) =
                __floats2half2_rn(sacc[ni][0], sacc[ni][1]);
            *(half2*)((char*)Ps + SWZ((row_s + g + 8) * 128 + (ni * 8 + 2 * t4) * 2)) =
                __floats2half2_rn(sacc[ni][2], sacc[ni][3]);
        }
        __syncwarp();

#pragma unroll
        for (int kb = 0; kb < 4; kb++) {
            unsigned a[4];
            ldmx4(a, (char*)Ps + SWZ((row_s + arow) * 128 + (kb * 16 + acol) * 2));
#pragma unroll
            for (int nip = 0; nip < 4; nip++) {
                unsigned bf[4];
                ldmx4(bf, (char*)Vts + SWZ((nip * 16 + brow) * 128 + (kb * 16 + bcol) * 2));
                mma16(oacc[nip * 2],     a, bf[0], bf[1]);
                mma16(oacc[nip * 2 + 1], a, bf[2], bf[3]);
            }
        }
    }

    // finalize -> g_ao fp16  [t*4+b][h*64+d]
    const float inv0 = 1.f / l0;
    const float inv1 = 1.f / l1;
    const int bb = bh >> 3;
    const int hh = bh & 7;
    const int q1 = qt * 64 + row_s + g;
    const int q2 = q1 + 8;
    __half* o1 = g_ao + ((size_t)q1 * 4 + bb) * 512 + hh * 64;
    __half* o2 = g_ao + ((size_t)q2 * 4 + bb) * 512 + hh * 64;
#pragma unroll
    for (int di = 0; di < 8; di++) {
        int d = di * 8 + 2 * t4;
        *(half2*)(o1 + d) = __floats2half2_rn(oacc[di][0] * inv0, oacc[di][1] * inv0);
        *(half2*)(o2 + d) = __floats2half2_rn(oacc[di][2] * inv1, oacc[di][3] * inv1);
    }
}

// ---------------------------------------------------------------------------
// Launch
// ---------------------------------------------------------------------------
extern "C" void kernel_launch(void* const* d_in, const int* in_sizes, int n_in,
                              void* d_out, int out_size) {
    (void)in_sizes; (void)n_in; (void)out_size;
    const float* query = (const float*)d_in[0];
    const float* dist  = (const float*)d_in[1];
    const float* inW   = (const float*)d_in[2];
    const float* inB   = (const float*)d_in[3];
    const float* outW  = (const float*)d_in[4];
    const float* outB  = (const float*)d_in[5];
    float* out = (float*)d_out;

    // 1. dist -> per-head contiguous fp16 bias
    bias_transpose_kernel<<<dim3(1024, 4), 512>>>(dist);

    // 2. QKV projection (fp16 tensor cores; scatter epilogue)
    gemm_f16_kernel<<<dim3(24, 64), 128>>>(query, inW, inB, nullptr, 0);

    // 3. fused attention
    attn_kernel<<<dim3(16, 32), 128>>>();

    // 4. output projection
    gemm_f16_kernel<<<dim3(8, 64), 128>>>(nullptr, outW, outB, out, 1);
}

// round 8
// speedup vs baseline: 2.8330x; 1.4315x over previous
#include <cuda_runtime.h>
#include <cuda_fp16.h>

#define T_DIM 1024
#define B_DIM 4
#define E_DIM 512
#define H_DIM 8
#define HD    64
#define BH    32
#define M_ROWS 4096

// ---------------------------------------------------------------------------
// Scratch
// ---------------------------------------------------------------------------
__device__ __half g_qh[BH * T_DIM * HD];          // scaled by 1/8
__device__ __half g_kh[BH * T_DIM * HD];
__device__ __half g_vh[BH * T_DIM * HD];          // normal layout [bh][t][d]
__device__ __half g_ao[M_ROWS * E_DIM];           // [t*4+b][e]
__device__ __half g_biash[(size_t)BH * T_DIM * T_DIM];  // 67 MB
__device__ __half g_qx[M_ROWS * E_DIM];           // query fp16
__device__ __half g_wa[3 * E_DIM * E_DIM];        // in_proj_weight fp16
__device__ __half g_wo[E_DIM * E_DIM];            // out_proj_weight fp16

// 128B-row swizzle: conflict-free ldmatrix + linear fills
__device__ __forceinline__ int SWZ(int b) { return b ^ ((b >> 3) & 0x70); }

__device__ __forceinline__ void ldmx4(unsigned r[4], const void* p) {
    unsigned addr = (unsigned)__cvta_generic_to_shared(p);
    asm volatile("ldmatrix.sync.aligned.m8n8.x4.shared.b16 {%0,%1,%2,%3},[%4];"
                 : "=r"(r[0]), "=r"(r[1]), "=r"(r[2]), "=r"(r[3]) : "r"(addr));
}
__device__ __forceinline__ void ldmx4t(unsigned r[4], const void* p) {
    unsigned addr = (unsigned)__cvta_generic_to_shared(p);
    asm volatile("ldmatrix.sync.aligned.m8n8.x4.trans.shared.b16 {%0,%1,%2,%3},[%4];"
                 : "=r"(r[0]), "=r"(r[1]), "=r"(r[2]), "=r"(r[3]) : "r"(addr));
}
__device__ __forceinline__ void mma16(float c[4], const unsigned a[4],
                                      unsigned b0, unsigned b1) {
    asm volatile(
        "mma.sync.aligned.m16n8k16.row.col.f32.f16.f16.f32 "
        "{%0,%1,%2,%3},{%4,%5,%6,%7},{%8,%9},{%0,%1,%2,%3};"
        : "+f"(c[0]), "+f"(c[1]), "+f"(c[2]), "+f"(c[3])
        : "r"(a[0]), "r"(a[1]), "r"(a[2]), "r"(a[3]), "r"(b0), "r"(b1));
}

#define CP16(dst, src) \
    asm volatile("cp.async.cg.shared.global [%0],[%1],16;" \
                 :: "r"((unsigned)__cvta_generic_to_shared(dst)), "l"(src))
#define CPCOMMIT() asm volatile("cp.async.commit_group;")
#define CPWAIT(n)  asm volatile("cp.async.wait_group %0;" :: "n"(n))

// ---------------------------------------------------------------------------
// Kernel 0: fp32 -> fp16 convert
// ---------------------------------------------------------------------------
__global__ void f2h_kernel(const float* __restrict__ src, __half* __restrict__ dst,
                           int n) {
    int i = (blockIdx.x * blockDim.x + threadIdx.x) * 4;
    if (i < n) {
        float4 x = *(const float4*)(src + i);
        *(half2*)(dst + i)     = __floats2half2_rn(x.x, x.y);
        *(half2*)(dst + i + 2) = __floats2half2_rn(x.z, x.w);
    }
}

// ---------------------------------------------------------------------------
// Kernel 1: dist [B,T,T,H] fp32 -> g_biash [B*H,T,T] fp16
// ---------------------------------------------------------------------------
__global__ void bias_transpose_kernel(const float* __restrict__ dist) {
    const int t = blockIdx.x;
    const int b = blockIdx.y;
    const int tid = threadIdx.x;   // 512 threads; s0 = 2*tid
    const float* src = dist + ((size_t)(b * T_DIM + t) * T_DIM + tid * 2) * H_DIM;
    float4 a0 = *(const float4*)(src);
    float4 a1 = *(const float4*)(src + 4);
    float4 b0 = *(const float4*)(src + 8);
    float4 b1 = *(const float4*)(src + 12);
    __half* dst = g_biash + (size_t)b * H_DIM * T_DIM * T_DIM
                + (size_t)t * T_DIM + tid * 2;
    const size_t hs = (size_t)T_DIM * T_DIM;
    *(half2*)(dst + 0 * hs) = __floats2half2_rn(a0.x, b0.x);
    *(half2*)(dst + 1 * hs) = __floats2half2_rn(a0.y, b0.y);
    *(half2*)(dst + 2 * hs) = __floats2half2_rn(a0.z, b0.z);
    *(half2*)(dst + 3 * hs) = __floats2half2_rn(a0.w, b0.w);
    *(half2*)(dst + 4 * hs) = __floats2half2_rn(a1.x, b1.x);
    *(half2*)(dst + 5 * hs) = __floats2half2_rn(a1.y, b1.y);
    *(half2*)(dst + 6 * hs) = __floats2half2_rn(a1.z, b1.z);
    *(half2*)(dst + 7 * hs) = __floats2half2_rn(a1.w, b1.w);
}

// ---------------------------------------------------------------------------
// Kernel 2/4: fp16 GEMM  C[M,N] = A[M,512] @ W[N,512]^T + bias
//   64x64 tile, BK=64, 128 threads, 3-stage cp.async pipeline.
// ---------------------------------------------------------------------------
__device__ __forceinline__ void qkv_store2(int m, int n, float v0, float v1,
                                           const float* __restrict__ bias) {
    v0 += bias[n]; v1 += bias[n + 1];
    const int sec = n >> 9;
    const int e   = n & 511;
    const int h   = e >> 6;
    const int d   = e & 63;
    const int tt  = m >> 2;
    const int bb  = m & 3;
    const size_t idx = ((size_t)(bb * 8 + h) * 1024 + tt) * 64 + d;
    if (sec == 0)      *(half2*)&g_qh[idx] = __floats2half2_rn(v0 * 0.125f, v1 * 0.125f);
    else if (sec == 1) *(half2*)&g_kh[idx] = __floats2half2_rn(v0, v1);
    else               *(half2*)&g_vh[idx] = __floats2half2_rn(v0, v1);
}

#define G_STAGE 4096   // halves per tile stage

__global__ void __launch_bounds__(128) gemm_f16_kernel(
    const __half* __restrict__ Ah, const __half* __restrict__ Wh,
    const float* __restrict__ bias, float* __restrict__ Cout, int mode) {
    extern __shared__ __half dsm[];
    __half* As = dsm;                 // [3][64*64]
    __half* Bs = dsm + 3 * G_STAGE;   // [3][64*64]

    const int tid  = threadIdx.x;
    const int lane = tid & 31;
    const int w    = tid >> 5;
    const int g    = lane >> 2;
    const int t4   = lane & 3;
    const int wm   = (w >> 1) * 32;
    const int wn   = (w & 1) * 32;
    const int bm0  = blockIdx.y * 64;
    const int bn0  = blockIdx.x * 64;

    const int arow = (lane & 7) + ((lane >> 3) & 1) * 8;
    const int acol = ((lane >> 4) & 1) * 8;
    const int brow = (lane & 7) + ((lane >> 4) & 1) * 8;
    const int bcol = ((lane >> 3) & 1) * 8;

    const int fr = tid >> 3;          // fill row 0..15
    const int fc = (tid & 7) * 8;     // fill col (halves)

    // issue one stage of cp.async fills
#define G_ISSUE(kt)                                                          \
    {                                                                        \
        __half* Ad = As + ((kt) % 3) * G_STAGE;                              \
        __half* Bd = Bs + ((kt) % 3) * G_STAGE;                              \
        _Pragma("unroll")                                                    \
        for (int i = 0; i < 4; i++) {                                        \
            int r = fr + i * 16;                                             \
            CP16((char*)Ad + SWZ(r * 128 + fc * 2),                          \
                 Ah + (size_t)(bm0 + r) * 512 + (kt) * 64 + fc);             \
            CP16((char*)Bd + SWZ(r * 128 + fc * 2),                          \
                 Wh + (size_t)(bn0 + r) * 512 + (kt) * 64 + fc);             \
        }                                                                    \
        CPCOMMIT();                                                          \
    }

    float acc[2][4][4];
#pragma unroll
    for (int mi = 0; mi < 2; mi++)
#pragma unroll
        for (int ni = 0; ni < 4; ni++)
#pragma unroll
            for (int i = 0; i < 4; i++) acc[mi][ni][i] = 0.f;

    G_ISSUE(0);
    G_ISSUE(1);

    for (int kt = 0; kt < 8; kt++) {
        if (kt < 7) { CPWAIT(1); } else { CPWAIT(0); }
        __syncthreads();
        if (kt + 2 < 8) G_ISSUE(kt + 2);

        __half* Ab = As + (kt % 3) * G_STAGE;
        __half* Bb = Bs + (kt % 3) * G_STAGE;
#pragma unroll
        for (int kb = 0; kb < 4; kb++) {
            unsigned a[2][4];
#pragma unroll
            for (int mi = 0; mi < 2; mi++)
                ldmx4(a[mi], (char*)Ab + SWZ((wm + mi * 16 + arow) * 128 + (kb * 16 + acol) * 2));
#pragma unroll
            for (int nip = 0; nip < 2; nip++) {
                unsigned bf[4];
                ldmx4(bf, (char*)Bb + SWZ((wn + nip * 16 + brow) * 128 + (kb * 16 + bcol) * 2));
#pragma unroll
                for (int mi = 0; mi < 2; mi++) {
                    mma16(acc[mi][nip * 2],     a[mi], bf[0], bf[1]);
                    mma16(acc[mi][nip * 2 + 1], a[mi], bf[2], bf[3]);
                }
            }
        }
        __syncthreads();
    }

#pragma unroll
    for (int mi = 0; mi < 2; mi++) {
#pragma unroll
        for (int ni = 0; ni < 4; ni++) {
            int m = bm0 + wm + mi * 16 + g;
            int n = bn0 + wn + ni * 8 + t4 * 2;
            if (mode == 0) {
                qkv_store2(m,     n, acc[mi][ni][0], acc[mi][ni][1], bias);
                qkv_store2(m + 8, n, acc[mi][ni][2], acc[mi][ni][3], bias);
            } else {
                *(float2*)&Cout[(size_t)m * 512 + n] =
                    make_float2(acc[mi][ni][0] + bias[n], acc[mi][ni][1] + bias[n + 1]);
                *(float2*)&Cout[(size_t)(m + 8) * 512 + n] =
                    make_float2(acc[mi][ni][2] + bias[n], acc[mi][ni][3] + bias[n + 1]);
            }
        }
    }
}
#define GEMM_SMEM_BYTES (6 * G_STAGE * 2)

// ---------------------------------------------------------------------------
// Kernel 3: fused flash attention, fp16 mma + ldmatrix, 2-stage cp.async
//   grid (8 q-tiles of 128 rows, 32 heads); 256 threads = 8 warps.
// Dynamic smem layout (halves):
//   Q [128*64] @0, P [128*64] @8192, K [2][64*64] @16384,
//   V [2][64*64] @24576, B [2][128*64] @32768. Total 49152 halves = 96KB.
// ---------------------------------------------------------------------------
#define A_OFF_P 8192
#define A_OFF_K 16384
#define A_OFF_V 24576
#define A_OFF_B 32768
#define ATT_SMEM_BYTES (49152 * 2)

__global__ void __launch_bounds__(256, 2) attn_kernel() {
    extern __shared__ __half dsm[];
    __half* Qs = dsm;
    __half* Ps = dsm + A_OFF_P;

    const int qt   = blockIdx.x;   // 0..7
    const int bh   = blockIdx.y;   // 0..31
    const int tid  = threadIdx.x;
    const int lane = tid & 31;
    const int w    = tid >> 5;
    const int g    = lane >> 2;
    const int t4   = lane & 3;
    const int row_s = w * 16;
    const int arow = (lane & 7) + ((lane >> 3) & 1) * 8;
    const int acol = ((lane >> 4) & 1) * 8;
    const int brow = (lane & 7) + ((lane >> 4) & 1) * 8;
    const int bcol = ((lane >> 3) & 1) * 8;

    const __half* __restrict__ Qg = g_qh + ((size_t)bh * 1024 + qt * 128) * 64;
    const __half* __restrict__ Kg = g_kh + (size_t)bh * 1024 * 64;
    const __half* __restrict__ Vg = g_vh + (size_t)bh * 1024 * 64;
    const __half* __restrict__ Bg = g_biash + ((size_t)bh * 1024 + qt * 128) * 1024;

    const int fr  = tid >> 3;          // 0..31
    const int fc  = (tid & 7) * 8;

#define A_ISSUE(st)                                                           \
    {                                                                         \
        __half* Kd = dsm + A_OFF_K + ((st) & 1) * 4096;                       \
        __half* Vd = dsm + A_OFF_V + ((st) & 1) * 4096;                       \
        __half* Bd = dsm + A_OFF_B + ((st) & 1) * 8192;                       \
        _Pragma("unroll")                                                     \
        for (int i = 0; i < 2; i++) {                                         \
            int r = fr + i * 32;                                              \
            CP16((char*)Kd + SWZ(r * 128 + fc * 2),                           \
                 Kg + (size_t)((st) * 64 + r) * 64 + fc);                     \
            CP16((char*)Vd + SWZ(r * 128 + fc * 2),                           \
                 Vg + (size_t)((st) * 64 + r) * 64 + fc);                     \
        }                                                                     \
        _Pragma("unroll")                                                     \
        for (int i = 0; i < 4; i++) {                                         \
            int r = fr + i * 32;                                              \
            CP16((char*)Bd + SWZ(r * 128 + fc * 2),                           \
                 Bg + (size_t)r * 1024 + (st) * 64 + fc);                     \
        }                                                                     \
        CPCOMMIT();                                                           \
    }

    A_ISSUE(0);

    // Q tile -> Qs (normal loads, overlap with stage-0 cp.async)
#pragma unroll
    for (int i = 0; i < 4; i++) {
        int idx = tid + i * 256;
        int r = idx >> 3, c8 = (idx & 7) * 8;
        *(uint4*)((char*)Qs + SWZ(r * 128 + c8 * 2)) = *(const uint4*)(Qg + r * 64 + c8);
    }

    float oacc[8][4];
#pragma unroll
    for (int di = 0; di < 8; di++)
#pragma unroll
        for (int i = 0; i < 4; i++) oacc[di][i] = 0.f;
    float m0 = -1e30f, m1 = -1e30f, l0 = 0.f, l1 = 0.f;

    for (int st = 0; st < 16; st++) {
        if (st + 1 < 16) A_ISSUE(st + 1);
        if (st < 15) { CPWAIT(1); } else { CPWAIT(0); }
        __syncthreads();

        __half* Kb = dsm + A_OFF_K + (st & 1) * 4096;
        __half* Vb = dsm + A_OFF_V + (st & 1) * 4096;
        __half* Bb = dsm + A_OFF_B + (st & 1) * 8192;

        // S = Q K^T  (warp: 16 q-rows x 64 s)
        float sacc[8][4];
#pragma unroll
        for (int ni = 0; ni < 8; ni++)
#pragma unroll
            for (int i = 0; i < 4; i++) sacc[ni][i] = 0.f;

#pragma unroll
        for (int kb = 0; kb < 4; kb++) {
            unsigned a[4];
            ldmx4(a, (char*)Qs + SWZ((row_s + arow) * 128 + (kb * 16 + acol) * 2));
#pragma unroll
            for (int nip = 0; nip < 4; nip++) {
                unsigned bf[4];
                ldmx4(bf, (char*)Kb + SWZ((nip * 16 + brow) * 128 + (kb * 16 + bcol) * 2));
                mma16(sacc[nip * 2],     a, bf[0], bf[1]);
                mma16(sacc[nip * 2 + 1], a, bf[2], bf[3]);
            }
        }

        // + bias, row max
        float mx0 = -1e30f, mx1 = -1e30f;
#pragma unroll
        for (int ni = 0; ni < 8; ni++) {
            half2 u1 = *(const half2*)((const char*)Bb +
                          SWZ((row_s + g) * 128 + (ni * 8 + 2 * t4) * 2));
            half2 u2 = *(const half2*)((const char*)Bb +
                          SWZ((row_s + g + 8) * 128 + (ni * 8 + 2 * t4) * 2));
            float2 z1 = __half22float2(u1);
            float2 z2 = __half22float2(u2);
            sacc[ni][0] += z1.x; sacc[ni][1] += z1.y;
            sacc[ni][2] += z2.x; sacc[ni][3] += z2.y;
            mx0 = fmaxf(mx0, fmaxf(sacc[ni][0], sacc[ni][1]));
            mx1 = fmaxf(mx1, fmaxf(sacc[ni][2], sacc[ni][3]));
        }
        mx0 = fmaxf(mx0, __shfl_xor_sync(0xffffffffu, mx0, 1));
        mx0 = fmaxf(mx0, __shfl_xor_sync(0xffffffffu, mx0, 2));
        mx1 = fmaxf(mx1, __shfl_xor_sync(0xffffffffu, mx1, 1));
        mx1 = fmaxf(mx1, __shfl_xor_sync(0xffffffffu, mx1, 2));

        float mn0 = fmaxf(m0, mx0), mn1 = fmaxf(m1, mx1);
        float sc0 = __expf(m0 - mn0), sc1 = __expf(m1 - mn1);
        m0 = mn0; m1 = mn1;

        float rs0 = 0.f, rs1 = 0.f;
#pragma unroll
        for (int ni = 0; ni < 8; ni++) {
            sacc[ni][0] = __expf(sacc[ni][0] - mn0);
            sacc[ni][1] = __expf(sacc[ni][1] - mn0);
            sacc[ni][2] = __expf(sacc[ni][2] - mn1);
            sacc[ni][3] = __expf(sacc[ni][3] - mn1);
            rs0 += sacc[ni][0] + sacc[ni][1];
            rs1 += sacc[ni][2] + sacc[ni][3];
        }
        rs0 += __shfl_xor_sync(0xffffffffu, rs0, 1);
        rs0 += __shfl_xor_sync(0xffffffffu, rs0, 2);
        rs1 += __shfl_xor_sync(0xffffffffu, rs1, 1);
        rs1 += __shfl_xor_sync(0xffffffffu, rs1, 2);
        l0 = l0 * sc0 + rs0;
        l1 = l1 * sc1 + rs1;

#pragma unroll
        for (int di = 0; di < 8; di++) {
            oacc[di][0] *= sc0; oacc[di][1] *= sc0;
            oacc[di][2] *= sc1; oacc[di][3] *= sc1;
        }

        // P -> smem fp16 (warp-private rows), then PV with trans-ldmatrix V
        __syncwarp();
#pragma unroll
        for (int ni = 0; ni < 8; ni++) {
            *(half2*)((char*)Ps + SWZ((row_s + g) * 128 + (ni * 8 + 2 * t4) * 2)) =
                __floats2half2_rn(sacc[ni][0], sacc[ni][1]);
            *(half2*)((char*)Ps + SWZ((row_s + g + 8) * 128 + (ni * 8 + 2 * t4) * 2)) =
                __floats2half2_rn(sacc[ni][2], sacc[ni][3]);
        }
        __syncwarp();

#pragma unroll
        for (int kb = 0; kb < 4; kb++) {          // kb over s
            unsigned a[4];
            ldmx4(a, (char*)Ps + SWZ((row_s + arow) * 128 + (kb * 16 + acol) * 2));
#pragma unroll
            for (int nip = 0; nip < 4; nip++) {   // nip over d
                unsigned bf[4];
                ldmx4t(bf, (char*)Vb + SWZ((kb * 16 + arow) * 128 + (nip * 16 + acol) * 2));
                mma16(oacc[nip * 2],     a, bf[0], bf[1]);
                mma16(oacc[nip * 2 + 1], a, bf[2], bf[3]);
            }
        }
        __syncthreads();
    }

    // finalize -> g_ao fp16  [t*4+b][h*64+d]
    const float inv0 = 1.f / l0;
    const float inv1 = 1.f / l1;
    const int bb = bh >> 3;
    const int hh = bh & 7;
    const int q1 = qt * 128 + row_s + g;
    const int q2 = q1 + 8;
    __half* o1 = g_ao + ((size_t)q1 * 4 + bb) * 512 + hh * 64;
    __half* o2 = g_ao + ((size_t)q2 * 4 + bb) * 512 + hh * 64;
#pragma unroll
    for (int di = 0; di < 8; di++) {
        int d = di * 8 + 2 * t4;
        *(half2*)(o1 + d) = __floats2half2_rn(oacc[di][0] * inv0, oacc[di][1] * inv0);
        *(half2*)(o2 + d) = __floats2half2_rn(oacc[di][2] * inv1, oacc[di][3] * inv1);
    }
}

// ---------------------------------------------------------------------------
// Launch
// ---------------------------------------------------------------------------
extern "C" void kernel_launch(void* const* d_in, const int* in_sizes, int n_in,
                              void* d_out, int out_size) {
    (void)in_sizes; (void)n_in; (void)out_size;
    const float* query = (const float*)d_in[0];
    const float* dist  = (const float*)d_in[1];
    const float* inW   = (const float*)d_in[2];
    const float* inB   = (const float*)d_in[3];
    const float* outW  = (const float*)d_in[4];
    const float* outB  = (const float*)d_in[5];
    float* out = (float*)d_out;

    static int configured = 0;
    if (!configured) {
        cudaFuncSetAttribute(gemm_f16_kernel,
                             cudaFuncAttributeMaxDynamicSharedMemorySize,
                             GEMM_SMEM_BYTES);
        cudaFuncSetAttribute(attn_kernel,
                             cudaFuncAttributeMaxDynamicSharedMemorySize,
                             ATT_SMEM_BYTES);
        configured = 1;
    }

    __half* qx; cudaGetSymbolAddress((void**)&qx, g_qx);
    __half* wa; cudaGetSymbolAddress((void**)&wa, g_wa);
    __half* wo; cudaGetSymbolAddress((void**)&wo, g_wo);

    // 0. fp32 -> fp16 converts
    f2h_kernel<<<(M_ROWS * E_DIM / 4 + 255) / 256, 256>>>(query, qx, M_ROWS * E_DIM);
    f2h_kernel<<<(3 * E_DIM * E_DIM / 4 + 255) / 256, 256>>>(inW, wa, 3 * E_DIM * E_DIM);
    f2h_kernel<<<(E_DIM * E_DIM / 4 + 255) / 256, 256>>>(outW, wo, E_DIM * E_DIM);

    // 1. dist -> per-head contiguous fp16 bias
    bias_transpose_kernel<<<dim3(1024, 4), 512>>>(dist);

    // 2. QKV projection
    gemm_f16_kernel<<<dim3(24, 64), 128, GEMM_SMEM_BYTES>>>(qx, wa, inB, nullptr, 0);

    // 3. fused attention
    attn_kernel<<<dim3(8, 32), 256, ATT_SMEM_BYTES>>>();

    // 4. output projection
    __half* ao; cudaGetSymbolAddress((void**)&ao, g_ao);
    gemm_f16_kernel<<<dim3(8, 64), 128, GEMM_SMEM_BYTES>>>(ao, wo, outB, out, 1);
}

// round 9
// speedup vs baseline: 2.9656x; 1.0468x over previous
#include <cuda_runtime.h>
#include <cuda_fp16.h>

#define T_DIM 1024
#define B_DIM 4
#define E_DIM 512
#define H_DIM 8
#define HD    64
#define BH    32
#define M_ROWS 4096

// ---------------------------------------------------------------------------
// Scratch
// ---------------------------------------------------------------------------
__device__ __half g_qh[BH * T_DIM * HD];          // scaled by 1/8
__device__ __half g_kh[BH * T_DIM * HD];
__device__ __half g_vh[BH * T_DIM * HD];          // normal layout [bh][t][d]
__device__ __half g_ao[M_ROWS * E_DIM];           // [t*4+b][e]
__device__ __half g_biash[(size_t)BH * T_DIM * T_DIM];  // 67 MB
__device__ __half g_qx[M_ROWS * E_DIM];           // query fp16
__device__ __half g_wa[3 * E_DIM * E_DIM];        // in_proj_weight fp16
__device__ __half g_wo[E_DIM * E_DIM];            // out_proj_weight fp16

// 128B-row swizzle: conflict-free ldmatrix + linear fills
__device__ __forceinline__ int SWZ(int b) { return b ^ ((b >> 3) & 0x70); }

__device__ __forceinline__ void ldmx4(unsigned r[4], const void* p) {
    unsigned addr = (unsigned)__cvta_generic_to_shared(p);
    asm volatile("ldmatrix.sync.aligned.m8n8.x4.shared.b16 {%0,%1,%2,%3},[%4];"
                 : "=r"(r[0]), "=r"(r[1]), "=r"(r[2]), "=r"(r[3]) : "r"(addr));
}
__device__ __forceinline__ void ldmx4t(unsigned r[4], const void* p) {
    unsigned addr = (unsigned)__cvta_generic_to_shared(p);
    asm volatile("ldmatrix.sync.aligned.m8n8.x4.trans.shared.b16 {%0,%1,%2,%3},[%4];"
                 : "=r"(r[0]), "=r"(r[1]), "=r"(r[2]), "=r"(r[3]) : "r"(addr));
}
__device__ __forceinline__ void mma16(float c[4], const unsigned a[4],
                                      unsigned b0, unsigned b1) {
    asm volatile(
        "mma.sync.aligned.m16n8k16.row.col.f32.f16.f16.f32 "
        "{%0,%1,%2,%3},{%4,%5,%6,%7},{%8,%9},{%0,%1,%2,%3};"
        : "+f"(c[0]), "+f"(c[1]), "+f"(c[2]), "+f"(c[3])
        : "r"(a[0]), "r"(a[1]), "r"(a[2]), "r"(a[3]), "r"(b0), "r"(b1));
}

#define CP16(dst, src) \
    asm volatile("cp.async.cg.shared.global [%0],[%1],16;" \
                 :: "r"((unsigned)__cvta_generic_to_shared(dst)), "l"(src))
#define CPCOMMIT() asm volatile("cp.async.commit_group;")
#define CPWAIT(n)  asm volatile("cp.async.wait_group %0;" :: "n"(n))

// ---------------------------------------------------------------------------
// Kernel 0: fp32 -> fp16 convert (two sources fused in one launch)
// ---------------------------------------------------------------------------
__global__ void f2h2_kernel(const float* __restrict__ s1, __half* __restrict__ d1,
                            int n1, const float* __restrict__ s2,
                            __half* __restrict__ d2, int n2) {
    int i = (blockIdx.x * blockDim.x + threadIdx.x) * 4;
    const float* s; __half* d;
    if (i < n1) { s = s1; d = d1; }
    else { i -= n1; if (i >= n2) return; s = s2; d = d2; }
    float4 x = *(const float4*)(s + i);
    *(half2*)(d + i)     = __floats2half2_rn(x.x, x.y);
    *(half2*)(d + i + 2) = __floats2half2_rn(x.z, x.w);
}

__global__ void f2h_kernel(const float* __restrict__ src, __half* __restrict__ dst,
                           int n) {
    int i = (blockIdx.x * blockDim.x + threadIdx.x) * 4;
    if (i < n) {
        float4 x = *(const float4*)(src + i);
        *(half2*)(dst + i)     = __floats2half2_rn(x.x, x.y);
        *(half2*)(dst + i + 2) = __floats2half2_rn(x.z, x.w);
    }
}

// ---------------------------------------------------------------------------
// Kernel 1: dist [B,T,T,H] fp32 -> g_biash [B*H,T,T] fp16
// ---------------------------------------------------------------------------
__global__ void bias_transpose_kernel(const float* __restrict__ dist) {
    const int t = blockIdx.x;
    const int b = blockIdx.y;
    const int tid = threadIdx.x;   // 512 threads; s0 = 2*tid
    const float* src = dist + ((size_t)(b * T_DIM + t) * T_DIM + tid * 2) * H_DIM;
    float4 a0 = *(const float4*)(src);
    float4 a1 = *(const float4*)(src + 4);
    float4 b0 = *(const float4*)(src + 8);
    float4 b1 = *(const float4*)(src + 12);
    __half* dst = g_biash + (size_t)b * H_DIM * T_DIM * T_DIM
                + (size_t)t * T_DIM + tid * 2;
    const size_t hs = (size_t)T_DIM * T_DIM;
    *(half2*)(dst + 0 * hs) = __floats2half2_rn(a0.x, b0.x);
    *(half2*)(dst + 1 * hs) = __floats2half2_rn(a0.y, b0.y);
    *(half2*)(dst + 2 * hs) = __floats2half2_rn(a0.z, b0.z);
    *(half2*)(dst + 3 * hs) = __floats2half2_rn(a0.w, b0.w);
    *(half2*)(dst + 4 * hs) = __floats2half2_rn(a1.x, b1.x);
    *(half2*)(dst + 5 * hs) = __floats2half2_rn(a1.y, b1.y);
    *(half2*)(dst + 6 * hs) = __floats2half2_rn(a1.z, b1.z);
    *(half2*)(dst + 7 * hs) = __floats2half2_rn(a1.w, b1.w);
}

// ---------------------------------------------------------------------------
// Kernel 2/4: fp16 GEMM  C[M,N] = A[M,512] @ W[N,512]^T + bias
//   64x64 tile, BK=64, 128 threads, 3-stage cp.async pipeline.
// ---------------------------------------------------------------------------
__device__ __forceinline__ void qkv_store2(int m, int n, float v0, float v1,
                                           const float* __restrict__ bias) {
    v0 += bias[n]; v1 += bias[n + 1];
    const int sec = n >> 9;
    const int e   = n & 511;
    const int h   = e >> 6;
    const int d   = e & 63;
    const int tt  = m >> 2;
    const int bb  = m & 3;
    const size_t idx = ((size_t)(bb * 8 + h) * 1024 + tt) * 64 + d;
    if (sec == 0)      *(half2*)&g_qh[idx] = __floats2half2_rn(v0 * 0.125f, v1 * 0.125f);
    else if (sec == 1) *(half2*)&g_kh[idx] = __floats2half2_rn(v0, v1);
    else               *(half2*)&g_vh[idx] = __floats2half2_rn(v0, v1);
}

#define G_STAGE 4096   // halves per tile stage

__global__ void __launch_bounds__(128) gemm_f16_kernel(
    const __half* __restrict__ Ah, const __half* __restrict__ Wh,
    const float* __restrict__ bias, float* __restrict__ Cout, int mode) {
    extern __shared__ __half dsm[];
    __half* As = dsm;                 // [3][64*64]
    __half* Bs = dsm + 3 * G_STAGE;   // [3][64*64]

    const int tid  = threadIdx.x;
    const int lane = tid & 31;
    const int w    = tid >> 5;
    const int g    = lane >> 2;
    const int t4   = lane & 3;
    const int wm   = (w >> 1) * 32;
    const int wn   = (w & 1) * 32;
    const int bm0  = blockIdx.y * 64;
    const int bn0  = blockIdx.x * 64;

    const int arow = (lane & 7) + ((lane >> 3) & 1) * 8;
    const int acol = ((lane >> 4) & 1) * 8;
    const int brow = (lane & 7) + ((lane >> 4) & 1) * 8;
    const int bcol = ((lane >> 3) & 1) * 8;

    const int fr = tid >> 3;          // fill row 0..15
    const int fc = (tid & 7) * 8;     // fill col (halves)

#define G_ISSUE(kt)                                                          \
    {                                                                        \
        __half* Ad = As + ((kt) % 3) * G_STAGE;                              \
        __half* Bd = Bs + ((kt) % 3) * G_STAGE;                              \
        _Pragma("unroll")                                                    \
        for (int i = 0; i < 4; i++) {                                        \
            int r = fr + i * 16;                                             \
            CP16((char*)Ad + SWZ(r * 128 + fc * 2),                          \
                 Ah + (size_t)(bm0 + r) * 512 + (kt) * 64 + fc);             \
            CP16((char*)Bd + SWZ(r * 128 + fc * 2),                          \
                 Wh + (size_t)(bn0 + r) * 512 + (kt) * 64 + fc);             \
        }                                                                    \
        CPCOMMIT();                                                          \
    }

    float acc[2][4][4];
#pragma unroll
    for (int mi = 0; mi < 2; mi++)
#pragma unroll
        for (int ni = 0; ni < 4; ni++)
#pragma unroll
            for (int i = 0; i < 4; i++) acc[mi][ni][i] = 0.f;

    G_ISSUE(0);
    G_ISSUE(1);

    for (int kt = 0; kt < 8; kt++) {
        if (kt < 7) { CPWAIT(1); } else { CPWAIT(0); }
        __syncthreads();
        if (kt + 2 < 8) G_ISSUE(kt + 2);

        __half* Ab = As + (kt % 3) * G_STAGE;
        __half* Bb = Bs + (kt % 3) * G_STAGE;
#pragma unroll
        for (int kb = 0; kb < 4; kb++) {
            unsigned a[2][4];
#pragma unroll
            for (int mi = 0; mi < 2; mi++)
                ldmx4(a[mi], (char*)Ab + SWZ((wm + mi * 16 + arow) * 128 + (kb * 16 + acol) * 2));
#pragma unroll
            for (int nip = 0; nip < 2; nip++) {
                unsigned bf[4];
                ldmx4(bf, (char*)Bb + SWZ((wn + nip * 16 + brow) * 128 + (kb * 16 + bcol) * 2));
#pragma unroll
                for (int mi = 0; mi < 2; mi++) {
                    mma16(acc[mi][nip * 2],     a[mi], bf[0], bf[1]);
                    mma16(acc[mi][nip * 2 + 1], a[mi], bf[2], bf[3]);
                }
            }
        }
        __syncthreads();
    }

#pragma unroll
    for (int mi = 0; mi < 2; mi++) {
#pragma unroll
        for (int ni = 0; ni < 4; ni++) {
            int m = bm0 + wm + mi * 16 + g;
            int n = bn0 + wn + ni * 8 + t4 * 2;
            if (mode == 0) {
                qkv_store2(m,     n, acc[mi][ni][0], acc[mi][ni][1], bias);
                qkv_store2(m + 8, n, acc[mi][ni][2], acc[mi][ni][3], bias);
            } else {
                *(float2*)&Cout[(size_t)m * 512 + n] =
                    make_float2(acc[mi][ni][0] + bias[n], acc[mi][ni][1] + bias[n + 1]);
                *(float2*)&Cout[(size_t)(m + 8) * 512 + n] =
                    make_float2(acc[mi][ni][2] + bias[n], acc[mi][ni][3] + bias[n + 1]);
            }
        }
    }
}
#define GEMM_SMEM_BYTES (6 * G_STAGE * 2)

// ---------------------------------------------------------------------------
// Kernel 3: fused flash attention, fp16 mma + ldmatrix, 2-stage cp.async
// ---------------------------------------------------------------------------
#define A_OFF_P 8192
#define A_OFF_K 16384
#define A_OFF_V 24576
#define A_OFF_B 32768
#define ATT_SMEM_BYTES (49152 * 2)

__global__ void __launch_bounds__(256, 2) attn_kernel() {
    extern __shared__ __half dsm[];
    __half* Qs = dsm;
    __half* Ps = dsm + A_OFF_P;

    const int qt   = blockIdx.x;   // 0..7
    const int bh   = blockIdx.y;   // 0..31
    const int tid  = threadIdx.x;
    const int lane = tid & 31;
    const int w    = tid >> 5;
    const int g    = lane >> 2;
    const int t4   = lane & 3;
    const int row_s = w * 16;
    const int arow = (lane & 7) + ((lane >> 3) & 1) * 8;
    const int acol = ((lane >> 4) & 1) * 8;
    const int brow = (lane & 7) + ((lane >> 4) & 1) * 8;
    const int bcol = ((lane >> 3) & 1) * 8;

    const __half* __restrict__ Qg = g_qh + ((size_t)bh * 1024 + qt * 128) * 64;
    const __half* __restrict__ Kg = g_kh + (size_t)bh * 1024 * 64;
    const __half* __restrict__ Vg = g_vh + (size_t)bh * 1024 * 64;
    const __half* __restrict__ Bg = g_biash + ((size_t)bh * 1024 + qt * 128) * 1024;

    const int fr  = tid >> 3;          // 0..31
    const int fc  = (tid & 7) * 8;

#define A_ISSUE(st)                                                           \
    {                                                                         \
        __half* Kd = dsm + A_OFF_K + ((st) & 1) * 4096;                       \
        __half* Vd = dsm + A_OFF_V + ((st) & 1) * 4096;                       \
        __half* Bd = dsm + A_OFF_B + ((st) & 1) * 8192;                       \
        _Pragma("unroll")                                                     \
        for (int i = 0; i < 2; i++) {                                         \
            int r = fr + i * 32;                                              \
            CP16((char*)Kd + SWZ(r * 128 + fc * 2),                           \
                 Kg + (size_t)((st) * 64 + r) * 64 + fc);                     \
            CP16((char*)Vd + SWZ(r * 128 + fc * 2),                           \
                 Vg + (size_t)((st) * 64 + r) * 64 + fc);                     \
        }                                                                     \
        _Pragma("unroll")                                                     \
        for (int i = 0; i < 4; i++) {                                         \
            int r = fr + i * 32;                                              \
            CP16((char*)Bd + SWZ(r * 128 + fc * 2),                           \
                 Bg + (size_t)r * 1024 + (st) * 64 + fc);                     \
        }                                                                     \
        CPCOMMIT();                                                           \
    }

    A_ISSUE(0);

    // Q tile -> Qs (normal loads, overlap with stage-0 cp.async)
#pragma unroll
    for (int i = 0; i < 4; i++) {
        int idx = tid + i * 256;
        int r = idx >> 3, c8 = (idx & 7) * 8;
        *(uint4*)((char*)Qs + SWZ(r * 128 + c8 * 2)) = *(const uint4*)(Qg + r * 64 + c8);
    }

    float oacc[8][4];
#pragma unroll
    for (int di = 0; di < 8; di++)
#pragma unroll
        for (int i = 0; i < 4; i++) oacc[di][i] = 0.f;
    float m0 = -1e30f, m1 = -1e30f, l0 = 0.f, l1 = 0.f;

    for (int st = 0; st < 16; st++) {
        if (st + 1 < 16) A_ISSUE(st + 1);
        if (st < 15) { CPWAIT(1); } else { CPWAIT(0); }
        __syncthreads();

        __half* Kb = dsm + A_OFF_K + (st & 1) * 4096;
        __half* Vb = dsm + A_OFF_V + (st & 1) * 4096;
        __half* Bb = dsm + A_OFF_B + (st & 1) * 8192;

        // S = Q K^T  (warp: 16 q-rows x 64 s)
        float sacc[8][4];
#pragma unroll
        for (int ni = 0; ni < 8; ni++)
#pragma unroll
            for (int i = 0; i < 4; i++) sacc[ni][i] = 0.f;

#pragma unroll
        for (int kb = 0; kb < 4; kb++) {
            unsigned a[4];
            ldmx4(a, (char*)Qs + SWZ((row_s + arow) * 128 + (kb * 16 + acol) * 2));
#pragma unroll
            for (int nip = 0; nip < 4; nip++) {
                unsigned bf[4];
                ldmx4(bf, (char*)Kb + SWZ((nip * 16 + brow) * 128 + (kb * 16 + bcol) * 2));
                mma16(sacc[nip * 2],     a, bf[0], bf[1]);
                mma16(sacc[nip * 2 + 1], a, bf[2], bf[3]);
            }
        }

        // + bias, row max
        float mx0 = -1e30f, mx1 = -1e30f;
#pragma unroll
        for (int ni = 0; ni < 8; ni++) {
            half2 u1 = *(const half2*)((const char*)Bb +
                          SWZ((row_s + g) * 128 + (ni * 8 + 2 * t4) * 2));
            half2 u2 = *(const half2*)((const char*)Bb +
                          SWZ((row_s + g + 8) * 128 + (ni * 8 + 2 * t4) * 2));
            float2 z1 = __half22float2(u1);
            float2 z2 = __half22float2(u2);
            sacc[ni][0] += z1.x; sacc[ni][1] += z1.y;
            sacc[ni][2] += z2.x; sacc[ni][3] += z2.y;
            mx0 = fmaxf(mx0, fmaxf(sacc[ni][0], sacc[ni][1]));
            mx1 = fmaxf(mx1, fmaxf(sacc[ni][2], sacc[ni][3]));
        }
        mx0 = fmaxf(mx0, __shfl_xor_sync(0xffffffffu, mx0, 1));
        mx0 = fmaxf(mx0, __shfl_xor_sync(0xffffffffu, mx0, 2));
        mx1 = fmaxf(mx1, __shfl_xor_sync(0xffffffffu, mx1, 1));
        mx1 = fmaxf(mx1, __shfl_xor_sync(0xffffffffu, mx1, 2));

        float mn0 = fmaxf(m0, mx0), mn1 = fmaxf(m1, mx1);
        float sc0 = __expf(m0 - mn0), sc1 = __expf(m1 - mn1);
        m0 = mn0; m1 = mn1;

        float rs0 = 0.f, rs1 = 0.f;
#pragma unroll
        for (int ni = 0; ni < 8; ni++) {
            sacc[ni][0] = __expf(sacc[ni][0] - mn0);
            sacc[ni][1] = __expf(sacc[ni][1] - mn0);
            sacc[ni][2] = __expf(sacc[ni][2] - mn1);
            sacc[ni][3] = __expf(sacc[ni][3] - mn1);
            rs0 += sacc[ni][0] + sacc[ni][1];
            rs1 += sacc[ni][2] + sacc[ni][3];
        }
        rs0 += __shfl_xor_sync(0xffffffffu, rs0, 1);
        rs0 += __shfl_xor_sync(0xffffffffu, rs0, 2);
        rs1 += __shfl_xor_sync(0xffffffffu, rs1, 1);
        rs1 += __shfl_xor_sync(0xffffffffu, rs1, 2);
        l0 = l0 * sc0 + rs0;
        l1 = l1 * sc1 + rs1;

#pragma unroll
        for (int di = 0; di < 8; di++) {
            oacc[di][0] *= sc0; oacc[di][1] *= sc0;
            oacc[di][2] *= sc1; oacc[di][3] *= sc1;
        }

        // P -> smem fp16 (warp-private rows), then PV with trans-ldmatrix V
        __syncwarp();
#pragma unroll
        for (int ni = 0; ni < 8; ni++) {
            *(half2*)((char*)Ps + SWZ((row_s + g) * 128 + (ni * 8 + 2 * t4) * 2)) =
                __floats2half2_rn(sacc[ni][0], sacc[ni][1]);
            *(half2*)((char*)Ps + SWZ((row_s + g + 8) * 128 + (ni * 8 + 2 * t4) * 2)) =
                __floats2half2_rn(sacc[ni][2], sacc[ni][3]);
        }
        __syncwarp();

#pragma unroll
        for (int kb = 0; kb < 4; kb++) {          // kb over s
            unsigned a[4];
            ldmx4(a, (char*)Ps + SWZ((row_s + arow) * 128 + (kb * 16 + acol) * 2));
#pragma unroll
            for (int nip = 0; nip < 4; nip++) {   // nip over d
                unsigned bf[4];
                ldmx4t(bf, (char*)Vb + SWZ((kb * 16 + arow) * 128 + (nip * 16 + acol) * 2));
                mma16(oacc[nip * 2],     a, bf[0], bf[1]);
                mma16(oacc[nip * 2 + 1], a, bf[2], bf[3]);
            }
        }
        __syncthreads();
    }

    // finalize -> g_ao fp16  [t*4+b][h*64+d]
    const float inv0 = 1.f / l0;
    const float inv1 = 1.f / l1;
    const int bb = bh >> 3;
    const int hh = bh & 7;
    const int q1 = qt * 128 + row_s + g;
    const int q2 = q1 + 8;
    __half* o1 = g_ao + ((size_t)q1 * 4 + bb) * 512 + hh * 64;
    __half* o2 = g_ao + ((size_t)q2 * 4 + bb) * 512 + hh * 64;
#pragma unroll
    for (int di = 0; di < 8; di++) {
        int d = di * 8 + 2 * t4;
        *(half2*)(o1 + d) = __floats2half2_rn(oacc[di][0] * inv0, oacc[di][1] * inv0);
        *(half2*)(o2 + d) = __floats2half2_rn(oacc[di][2] * inv1, oacc[di][3] * inv1);
    }
}

// ---------------------------------------------------------------------------
// Launch: fork bias_transpose (+wo convert) onto a side stream, overlapped
// with converts + QKV GEMM; join before attention.
// ---------------------------------------------------------------------------
extern "C" void kernel_launch(void* const* d_in, const int* in_sizes, int n_in,
                              void* d_out, int out_size) {
    (void)in_sizes; (void)n_in; (void)out_size;
    const float* query = (const float*)d_in[0];
    const float* dist  = (const float*)d_in[1];
    const float* inW   = (const float*)d_in[2];
    const float* inB   = (const float*)d_in[3];
    const float* outW  = (const float*)d_in[4];
    const float* outB  = (const float*)d_in[5];
    float* out = (float*)d_out;

    static cudaStream_t s2 = nullptr;
    static cudaEvent_t evFork = nullptr, evJoin = nullptr;
    if (!s2) {
        cudaStreamCreateWithFlags(&s2, cudaStreamNonBlocking);
        cudaEventCreateWithFlags(&evFork, cudaEventDisableTiming);
        cudaEventCreateWithFlags(&evJoin, cudaEventDisableTiming);
        cudaFuncSetAttribute(gemm_f16_kernel,
                             cudaFuncAttributeMaxDynamicSharedMemorySize,
                             GEMM_SMEM_BYTES);
        cudaFuncSetAttribute(attn_kernel,
                             cudaFuncAttributeMaxDynamicSharedMemorySize,
                             ATT_SMEM_BYTES);
    }

    __half* qx; cudaGetSymbolAddress((void**)&qx, g_qx);
    __half* wa; cudaGetSymbolAddress((void**)&wa, g_wa);
    __half* wo; cudaGetSymbolAddress((void**)&wo, g_wo);
    __half* ao; cudaGetSymbolAddress((void**)&ao, g_ao);

    // ---- fork: side stream does the DRAM-bound transpose + wo convert ----
    cudaEventRecord(evFork, 0);
    cudaStreamWaitEvent(s2, evFork, 0);
    bias_transpose_kernel<<<dim3(1024, 4), 512, 0, s2>>>(dist);
    f2h_kernel<<<(E_DIM * E_DIM / 4 + 255) / 256, 256, 0, s2>>>(
        outW, wo, E_DIM * E_DIM);
    cudaEventRecord(evJoin, s2);

    // ---- main stream: converts + QKV projection (compute-bound) ----
    {
        const int n1 = M_ROWS * E_DIM;
        const int n2 = 3 * E_DIM * E_DIM;
        f2h2_kernel<<<((n1 + n2) / 4 + 255) / 256, 256>>>(query, qx, n1, inW, wa, n2);
    }
    gemm_f16_kernel<<<dim3(24, 64), 128, GEMM_SMEM_BYTES>>>(qx, wa, inB, nullptr, 0);

    // ---- join, then attention + output projection ----
    cudaStreamWaitEvent(0, evJoin, 0);
    attn_kernel<<<dim3(8, 32), 256, ATT_SMEM_BYTES>>>();
    gemm_f16_kernel<<<dim3(8, 64), 128, GEMM_SMEM_BYTES>>>(ao, wo, outB, out, 1);
}